// round 8
// baseline (speedup 1.0000x reference)
#include <cuda_runtime.h>
#include <cuda_bf16.h>
#include <cuda_fp16.h>
#include <cstdint>

// ---------------------------------------------------------------------------
// GCN encoder: N=50000, E=500000, 128 -> 256 -> 512 -> 128
// CSR gather aggregation (BN fused, fp16 activations, 2x edge unroll)
// + fp16 tensor-core GEMM pipelines (ldmatrix frag loads, fused BN stats)
// ---------------------------------------------------------------------------

#define MAXN 50048
#define MAXE 524288
#define EPS 1e-5f
#define SCAN_BLK 1024

__device__ float  g_dinv[MAXN];
__device__ int    g_cnt[MAXN];
__device__ int    g_rowptr[MAXN + 1];
__device__ int    g_cursor[MAXN];
__device__ int    g_bsum[64];
__device__ int2   g_adj[MAXE];                 // (src, bits(w))
__device__ __half g_agg1h[(size_t)MAXN * 128];
__device__ __half g_agg2h[(size_t)MAXN * 256];
__device__ __half g_h1[(size_t)MAXN * 256];    // fp16 raw (pre-BN)
__device__ __half g_h2[(size_t)MAXN * 512];
__device__ __half g_w1t[256 * 128];            // fp16 W1^T [N][K]
__device__ __half g_w2t[512 * 256];
__device__ __half g_wlt[128 * 512];
__device__ float2 g_stats1[256];
__device__ float2 g_stats2[512];
__device__ float2 g_ss1[256];
__device__ float2 g_ss2[512];
__device__ int    g_flag32;

// ---------------------------------------------------------------------------

__device__ __forceinline__ void red_add_v2(float2* addr, float a, float b) {
    asm volatile("red.global.add.v2.f32 [%0], {%1,%2};"
                 :: "l"(addr), "f"(a), "f"(b) : "memory");
}

__device__ __forceinline__ int load_idx(const void* ei, long long pos, int is32) {
    if (is32) return ((const int*)ei)[pos];
    return (int)(((const long long*)ei)[pos]);
}

__device__ __forceinline__ uint32_t pack_h2(float lo, float hi) {
    uint32_t u;
    asm("cvt.rn.f16x2.f32 %0, %1, %2;" : "=r"(u) : "f"(hi), "f"(lo));
    return u;
}

__device__ __forceinline__ float2 unpack_h2(uint32_t u) {
    __half2 h = *(__half2*)&u;
    return __half22float2(h);
}

__device__ __forceinline__ void cp_async16(void* sptr, const void* gptr, int src_bytes) {
    uint32_t sa = (uint32_t)__cvta_generic_to_shared(sptr);
    asm volatile("cp.async.cg.shared.global [%0], [%1], 16, %2;"
                 :: "r"(sa), "l"(gptr), "r"(src_bytes));
}

__device__ __forceinline__ void ldsm_x4(uint32_t& r0, uint32_t& r1,
                                        uint32_t& r2, uint32_t& r3,
                                        const void* smem_ptr) {
    uint32_t sa = (uint32_t)__cvta_generic_to_shared(smem_ptr);
    asm volatile("ldmatrix.sync.aligned.m8n8.x4.shared.b16 {%0,%1,%2,%3}, [%4];"
                 : "=r"(r0), "=r"(r1), "=r"(r2), "=r"(r3) : "r"(sa));
}

// --- prep0 (+fused dtype detect on block 0): zero cnt + stats ----------------
__global__ void k_prep0(const int* __restrict__ ei32, long long E,
                        int* cnt, int n, float2* st1, float2* st2,
                        int d1, int d2, int* flag) {
    int i = blockIdx.x * blockDim.x + threadIdx.x;
    if (blockIdx.x == 0) {
        long long lim = E < 8192 ? E : 8192;
        int any = 0;
        for (long long j = threadIdx.x; j < lim; j += blockDim.x)
            if (ei32[2 * j + 1] != 0) any = 1;
        if (any) atomicOr(flag, 1);
    }
    if (i < n) cnt[i] = 0;
    if (i < d1) st1[i] = make_float2(0.f, 0.f);
    if (i < d2) st2[i] = make_float2(0.f, 0.f);
}

// --- in-degree counts ---------------------------------------------------------
__global__ void k_count(const void* ei, long long E, const int* flag, int* cnt) {
    long long i = blockIdx.x * (long long)blockDim.x + threadIdx.x;
    long long stride = (long long)gridDim.x * blockDim.x;
    int is32 = *flag;
    for (; i < E; i += stride) {
        int d = load_idx(ei, E + i, is32);
        atomicAdd(&cnt[d], 1);
    }
}

// --- scan pass 1: per-block sums -----------------------------------------------
__global__ __launch_bounds__(SCAN_BLK) void k_scan_red(const int* __restrict__ cnt,
                                                       int* __restrict__ bsum, int n) {
    int i = blockIdx.x * SCAN_BLK + threadIdx.x;
    int v = (i < n) ? cnt[i] : 0;
    int lane = threadIdx.x & 31, wid = threadIdx.x >> 5;
#pragma unroll
    for (int off = 16; off; off >>= 1) v += __shfl_xor_sync(0xffffffffu, v, off);
    __shared__ int ws[32];
    if (lane == 0) ws[wid] = v;
    __syncthreads();
    if (wid == 0) {
        v = ws[lane];
#pragma unroll
        for (int off = 16; off; off >>= 1) v += __shfl_xor_sync(0xffffffffu, v, off);
        if (lane == 0) bsum[blockIdx.x] = v;
    }
}

// --- scan pass 2: block offset + local scan + apply -----------------------------
__global__ __launch_bounds__(SCAN_BLK) void k_scan_apply(const int* __restrict__ cnt,
                                                         const int* __restrict__ bsum, int nb,
                                                         int* __restrict__ rowptr,
                                                         int* __restrict__ cursor,
                                                         float* __restrict__ dinv, int n) {
    int tid = threadIdx.x;
    int lane = tid & 31, wid = tid >> 5;
    __shared__ int ws[32];
    __shared__ int s_off;

    int b = (tid < nb && tid < blockIdx.x) ? bsum[tid] : 0;
#pragma unroll
    for (int off = 16; off; off >>= 1) b += __shfl_xor_sync(0xffffffffu, b, off);
    if (lane == 0) ws[wid] = b;
    __syncthreads();
    if (wid == 0) {
        int w = ws[lane];
#pragma unroll
        for (int off = 16; off; off >>= 1) w += __shfl_xor_sync(0xffffffffu, w, off);
        if (lane == 0) s_off = w;
    }
    __syncthreads();
    int offset = s_off;
    __syncthreads();

    int i = blockIdx.x * SCAN_BLK + tid;
    int v = (i < n) ? cnt[i] : 0;
    int x = v;
#pragma unroll
    for (int off = 1; off < 32; off <<= 1) {
        int y = __shfl_up_sync(0xffffffffu, x, off);
        if (lane >= off) x += y;
    }
    if (lane == 31) ws[wid] = x;
    __syncthreads();
    if (wid == 0) {
        int w = ws[lane];
#pragma unroll
        for (int off = 1; off < 32; off <<= 1) {
            int y = __shfl_up_sync(0xffffffffu, w, off);
            if (lane >= off) w += y;
        }
        ws[lane] = w;
    }
    __syncthreads();
    int incl = x + (wid > 0 ? ws[wid - 1] : 0);
    int excl = incl - v + offset;
    if (i < n) {
        rowptr[i] = excl;
        cursor[i] = excl;
        dinv[i] = rsqrtf((float)v + 1.0f);
        if (i == n - 1) rowptr[n] = excl + v;
    }
}

// --- bucket-fill adjacency -------------------------------------------------------
__global__ void k_fill(const void* __restrict__ ei, long long E, const int* flag,
                       const float* __restrict__ dinv, int* __restrict__ cursor,
                       int2* __restrict__ adj) {
    long long i = blockIdx.x * (long long)blockDim.x + threadIdx.x;
    long long stride = (long long)gridDim.x * blockDim.x;
    int is32 = *flag;
    for (; i < E; i += stride) {
        int s = load_idx(ei, i, is32);
        int d = load_idx(ei, E + i, is32);
        float w = dinv[s] * dinv[d];
        int pos = atomicAdd(&cursor[d], 1);
        adj[pos] = make_int2(s, __float_as_int(w));
    }
}

// --- weight convert: all three -> fp16 transposed [N][K] --------------------------
__global__ void k_cvtw(const float* __restrict__ W1, const float* __restrict__ W2,
                       const float* __restrict__ W3,
                       __half* __restrict__ t1, __half* __restrict__ t2,
                       __half* __restrict__ t3,
                       int K1, int N1, int K2, int N2, int K3, int N3) {
    int i = blockIdx.x * blockDim.x + threadIdx.x;
    if (i < K1 * N1) {
        int k = i / N1, n = i % N1;
        t1[n * K1 + k] = __float2half_rn(W1[i]);
    }
    if (i < K2 * N2) {
        int k = i / N2, n = i % N2;
        t2[n * K2 + k] = __float2half_rn(W2[i]);
    }
    if (i < K3 * N3) {
        int k = i / N3, n = i % N3;
        t3[n * K3 + k] = __float2half_rn(W3[i]);
    }
}

// --- agg layer 1: fp32 x in, fp16 out, 2x edge unroll ------------------------------
__global__ __launch_bounds__(256) void k_agg1(const int2* __restrict__ adj,
                                              const int* __restrict__ rowptr,
                                              const float* __restrict__ dinv,
                                              const float* __restrict__ X,
                                              __half* __restrict__ out, int N) {
    int node = (blockIdx.x * blockDim.x + threadIdx.x) >> 5;
    int lane = threadIdx.x & 31;
    if (node >= N) return;
    float w0 = dinv[node]; w0 *= w0;
    float4 a = ((const float4*)(X + (size_t)node * 128))[lane];
    float4 acc = make_float4(a.x * w0, a.y * w0, a.z * w0, a.w * w0);
    float4 acc2 = make_float4(0.f, 0.f, 0.f, 0.f);
    int j = rowptr[node], end = rowptr[node + 1];
    for (; j + 2 <= end; j += 2) {
        int2 e0 = adj[j];
        int2 e1 = adj[j + 1];
        float wa = __int_as_float(e0.y), wb = __int_as_float(e1.y);
        float4 s0 = ((const float4*)(X + (size_t)e0.x * 128))[lane];
        float4 s1 = ((const float4*)(X + (size_t)e1.x * 128))[lane];
        acc.x  += wa * s0.x; acc.y  += wa * s0.y; acc.z  += wa * s0.z; acc.w  += wa * s0.w;
        acc2.x += wb * s1.x; acc2.y += wb * s1.y; acc2.z += wb * s1.z; acc2.w += wb * s1.w;
    }
    if (j < end) {
        int2 e0 = adj[j];
        float wa = __int_as_float(e0.y);
        float4 s0 = ((const float4*)(X + (size_t)e0.x * 128))[lane];
        acc.x += wa * s0.x; acc.y += wa * s0.y; acc.z += wa * s0.z; acc.w += wa * s0.w;
    }
    acc.x += acc2.x; acc.y += acc2.y; acc.z += acc2.z; acc.w += acc2.w;
    ((uint2*)(out + (size_t)node * 128))[lane] =
        make_uint2(pack_h2(acc.x, acc.y), pack_h2(acc.z, acc.w));
}

// --- agg layer 2: fp16 h1 in (BN+ReLU fused), fp16 out, 2x edge unroll -------------
__global__ __launch_bounds__(256) void k_agg2(const int2* __restrict__ adj,
                                              const int* __restrict__ rowptr,
                                              const float* __restrict__ dinv,
                                              const __half* __restrict__ X,
                                              __half* __restrict__ out, int N,
                                              const float2* __restrict__ ss) {
    int node = (blockIdx.x * blockDim.x + threadIdx.x) >> 5;
    int lane = threadIdx.x & 31;
    if (node >= N) return;
    float2 sr[8];
#pragma unroll
    for (int j = 0; j < 8; j++) sr[j] = ss[lane * 8 + j];

    auto gather = [&](int src, float* f) {
        uint4 u = ((const uint4*)(X + (size_t)src * 256))[lane];
        float2 f0 = unpack_h2(u.x), f1 = unpack_h2(u.y);
        float2 f2 = unpack_h2(u.z), f3 = unpack_h2(u.w);
        f[0] = fmaxf(fmaf(f0.x, sr[0].x, sr[0].y), 0.f);
        f[1] = fmaxf(fmaf(f0.y, sr[1].x, sr[1].y), 0.f);
        f[2] = fmaxf(fmaf(f1.x, sr[2].x, sr[2].y), 0.f);
        f[3] = fmaxf(fmaf(f1.y, sr[3].x, sr[3].y), 0.f);
        f[4] = fmaxf(fmaf(f2.x, sr[4].x, sr[4].y), 0.f);
        f[5] = fmaxf(fmaf(f2.y, sr[5].x, sr[5].y), 0.f);
        f[6] = fmaxf(fmaf(f3.x, sr[6].x, sr[6].y), 0.f);
        f[7] = fmaxf(fmaf(f3.y, sr[7].x, sr[7].y), 0.f);
    };

    float acc[8], acc2[8];
    float w0 = dinv[node]; w0 *= w0;
    {
        float f[8];
        gather(node, f);
#pragma unroll
        for (int j = 0; j < 8; j++) { acc[j] = w0 * f[j]; acc2[j] = 0.f; }
    }
    int j = rowptr[node], end = rowptr[node + 1];
    for (; j + 2 <= end; j += 2) {
        int2 e0 = adj[j];
        int2 e1 = adj[j + 1];
        float wa = __int_as_float(e0.y), wb = __int_as_float(e1.y);
        float fa[8], fb[8];
        gather(e0.x, fa);
        gather(e1.x, fb);
#pragma unroll
        for (int jj = 0; jj < 8; jj++) {
            acc[jj]  += wa * fa[jj];
            acc2[jj] += wb * fb[jj];
        }
    }
    if (j < end) {
        int2 e0 = adj[j];
        float wa = __int_as_float(e0.y);
        float fa[8];
        gather(e0.x, fa);
#pragma unroll
        for (int jj = 0; jj < 8; jj++) acc[jj] += wa * fa[jj];
    }
#pragma unroll
    for (int jj = 0; jj < 8; jj++) acc[jj] += acc2[jj];
    uint4 o;
    o.x = pack_h2(acc[0], acc[1]);
    o.y = pack_h2(acc[2], acc[3]);
    o.z = pack_h2(acc[4], acc[5]);
    o.w = pack_h2(acc[6], acc[7]);
    ((uint4*)(out + (size_t)node * 256))[lane] = o;
}

// ---------------------------------------------------------------------------
// fp16 pipelined GEMM with ldmatrix frag loads. Block 128x128, 8 warps, BK=32.
// C stored fp16 (raw pre-BN) + fused fp32 BN stats.
// ---------------------------------------------------------------------------
#define GBM 128
#define GBN 128
#define HASTR 40
#define HTSZ (128 * HASTR)
#define SMEM_H ((4 * HTSZ) * 2)
#define SMEM_FINH (SMEM_H + 512 * 8)

__global__ __launch_bounds__(256) void k_gemm_h(const __half* __restrict__ A,
                                                const __half* __restrict__ Bt,
                                                const float* __restrict__ bias,
                                                __half* __restrict__ C,
                                                float2* __restrict__ stats,
                                                int M, int N, int K) {
    extern __shared__ __half smh[];
    __half* As = smh;
    __half* Bs = smh + 2 * HTSZ;

    const int tid  = threadIdx.x;
    const int lane = tid & 31;
    const int warpId = tid >> 5;
    const int warpM = warpId & 3;
    const int warpN = warpId >> 2;
    const int g = lane >> 2;
    const int t = lane & 3;
    const int bm = blockIdx.y * GBM;
    const int bn = blockIdx.x * GBN;

    // ldmatrix lane->address mapping
    const int tl = lane >> 3, r8 = lane & 7;
    const int a_r = ((tl & 1) << 3) + r8;   // row within 16
    const int a_c = (tl >> 1) << 3;         // col 0/8
    const int b_r = ((tl >> 1) << 3) + r8;
    const int b_c = (tl & 1) << 3;

    const int l_row = tid >> 2;
    const int l_chk = (tid & 3) * 8;

    float4 acc[2][8];
#pragma unroll
    for (int i = 0; i < 2; i++)
#pragma unroll
        for (int j = 0; j < 8; j++)
            acc[i][j] = make_float4(0.f, 0.f, 0.f, 0.f);

    auto load_stage = [&](int stg, int k0) {
        __half* pa = As + stg * HTSZ;
        __half* pb = Bs + stg * HTSZ;
#pragma unroll
        for (int i = 0; i < 2; i++) {
            int row = i * 64 + l_row;
            int gm = bm + row;
            int ok = (gm < M) ? 16 : 0;
            int gmc = min(gm, M - 1);
            cp_async16(pa + row * HASTR + l_chk, A + (size_t)gmc * K + k0 + l_chk, ok);
        }
#pragma unroll
        for (int i = 0; i < 2; i++) {
            int row = i * 64 + l_row;
            cp_async16(pb + row * HASTR + l_chk, Bt + (size_t)(bn + row) * K + k0 + l_chk, 16);
        }
    };

    const int nk = K / 32;
    load_stage(0, 0);
    asm volatile("cp.async.commit_group;");

    for (int tk = 0; tk < nk; tk++) {
        if (tk + 1 < nk) {
            load_stage((tk + 1) & 1, (tk + 1) * 32);
            asm volatile("cp.async.commit_group;");
            asm volatile("cp.async.wait_group 1;");
        } else {
            asm volatile("cp.async.wait_group 0;");
        }
        __syncthreads();

        const __half* pa = As + (tk & 1) * HTSZ;
        const __half* pb = Bs + (tk & 1) * HTSZ;
#pragma unroll
        for (int kk = 0; kk < 32; kk += 16) {
            uint32_t afrag[2][4];
            uint32_t bfrag[8][2];
#pragma unroll
            for (int im = 0; im < 2; im++)
                ldsm_x4(afrag[im][0], afrag[im][1], afrag[im][2], afrag[im][3],
                        pa + (warpM * 32 + im * 16 + a_r) * HASTR + kk + a_c);
#pragma unroll
            for (int jp = 0; jp < 4; jp++)
                ldsm_x4(bfrag[2*jp][0], bfrag[2*jp][1], bfrag[2*jp+1][0], bfrag[2*jp+1][1],
                        pb + (warpN * 64 + jp * 16 + b_r) * HASTR + kk + b_c);
#pragma unroll
            for (int im = 0; im < 2; im++)
#pragma unroll
                for (int jn = 0; jn < 8; jn++) {
                    float4& c = acc[im][jn];
                    asm volatile(
                        "mma.sync.aligned.m16n8k16.row.col.f32.f16.f16.f32 "
                        "{%0,%1,%2,%3}, {%4,%5,%6,%7}, {%8,%9}, {%0,%1,%2,%3};"
                        : "+f"(c.x), "+f"(c.y), "+f"(c.z), "+f"(c.w)
                        : "r"(afrag[im][0]), "r"(afrag[im][1]),
                          "r"(afrag[im][2]), "r"(afrag[im][3]),
                          "r"(bfrag[jn][0]), "r"(bfrag[jn][1]));
                }
        }
        __syncthreads();
    }

#pragma unroll
    for (int jn = 0; jn < 8; jn++) {
        int col = bn + warpN * 64 + jn * 8 + 2 * t;
        float bx = bias[col], by = bias[col + 1];
        float s0 = 0.f, q0 = 0.f, s1 = 0.f, q1 = 0.f;
#pragma unroll
        for (int im = 0; im < 2; im++) {
            int row0 = bm + warpM * 32 + im * 16 + g;
            float4 c = acc[im][jn];
            if (row0 < M) {
                float ox = c.x + bx, oy = c.y + by;
                *(uint32_t*)(C + (size_t)row0 * N + col) = pack_h2(ox, oy);
                s0 += ox; q0 += ox * ox; s1 += oy; q1 += oy * oy;
            }
            if (row0 + 8 < M) {
                float oz = c.z + bx, ow = c.w + by;
                *(uint32_t*)(C + (size_t)(row0 + 8) * N + col) = pack_h2(oz, ow);
                s0 += oz; q0 += oz * oz; s1 += ow; q1 += ow * ow;
            }
        }
#pragma unroll
        for (int m = 4; m < 32; m <<= 1) {
            s0 += __shfl_xor_sync(0xffffffffu, s0, m);
            q0 += __shfl_xor_sync(0xffffffffu, q0, m);
            s1 += __shfl_xor_sync(0xffffffffu, s1, m);
            q1 += __shfl_xor_sync(0xffffffffu, q1, m);
        }
        if (g == 0) {
            red_add_v2(&stats[col], s0, q0);
            red_add_v2(&stats[col + 1], s1, q1);
        }
    }
}

// ---------------------------------------------------------------------------
// Final fp16 GEMM: ldmatrix loads, BN2+ReLU applied to A frags in registers.
// ---------------------------------------------------------------------------
__global__ __launch_bounds__(256) void k_gemm_finh(const __half* __restrict__ A,
                                                   const __half* __restrict__ Bt,
                                                   const float* __restrict__ bias,
                                                   float* __restrict__ C,
                                                   const float2* __restrict__ ssA,
                                                   int M, int N, int K) {
    extern __shared__ __half smh[];
    __half* As = smh;
    __half* Bs = smh + 2 * HTSZ;
    float2* ssm = (float2*)(smh + 4 * HTSZ);

    const int tid  = threadIdx.x;
    const int lane = tid & 31;
    const int warpId = tid >> 5;
    const int warpM = warpId & 3;
    const int warpN = warpId >> 2;
    const int g = lane >> 2;
    const int t = lane & 3;
    const int bm = blockIdx.y * GBM;
    const int bn = blockIdx.x * GBN;

    const int tl = lane >> 3, r8 = lane & 7;
    const int a_r = ((tl & 1) << 3) + r8;
    const int a_c = (tl >> 1) << 3;
    const int b_r = ((tl >> 1) << 3) + r8;
    const int b_c = (tl & 1) << 3;

    for (int c = tid; c < K; c += 256) ssm[c] = ssA[c];

    const int l_row = tid >> 2;
    const int l_chk = (tid & 3) * 8;

    float4 acc[2][8];
#pragma unroll
    for (int i = 0; i < 2; i++)
#pragma unroll
        for (int j = 0; j < 8; j++)
            acc[i][j] = make_float4(0.f, 0.f, 0.f, 0.f);

    auto load_stage = [&](int stg, int k0) {
        __half* pa = As + stg * HTSZ;
        __half* pb = Bs + stg * HTSZ;
#pragma unroll
        for (int i = 0; i < 2; i++) {
            int row = i * 64 + l_row;
            int gm = bm + row;
            int ok = (gm < M) ? 16 : 0;
            int gmc = min(gm, M - 1);
            cp_async16(pa + row * HASTR + l_chk, A + (size_t)gmc * K + k0 + l_chk, ok);
        }
#pragma unroll
        for (int i = 0; i < 2; i++) {
            int row = i * 64 + l_row;
            cp_async16(pb + row * HASTR + l_chk, Bt + (size_t)(bn + row) * K + k0 + l_chk, 16);
        }
    };

    const int nk = K / 32;
    load_stage(0, 0);
    asm volatile("cp.async.commit_group;");

    for (int tk = 0; tk < nk; tk++) {
        if (tk + 1 < nk) {
            load_stage((tk + 1) & 1, (tk + 1) * 32);
            asm volatile("cp.async.commit_group;");
            asm volatile("cp.async.wait_group 1;");
        } else {
            asm volatile("cp.async.wait_group 0;");
        }
        __syncthreads();

        const __half* pa = As + (tk & 1) * HTSZ;
        const __half* pb = Bs + (tk & 1) * HTSZ;
        const int kbase = tk * 32;
#pragma unroll
        for (int kk = 0; kk < 32; kk += 16) {
            int kc = kbase + kk + 2 * t;
            float2 s0 = ssm[kc],     s1 = ssm[kc + 1];
            float2 s2 = ssm[kc + 8], s3 = ssm[kc + 9];
            uint32_t afrag[2][4];
            uint32_t bfrag[8][2];
#pragma unroll
            for (int im = 0; im < 2; im++) {
                uint32_t raw[4];
                ldsm_x4(raw[0], raw[1], raw[2], raw[3],
                        pa + (warpM * 32 + im * 16 + a_r) * HASTR + kk + a_c);
                float2 f0 = unpack_h2(raw[0]);
                float2 f1 = unpack_h2(raw[1]);
                float2 f2 = unpack_h2(raw[2]);
                float2 f3 = unpack_h2(raw[3]);
                afrag[im][0] = pack_h2(fmaxf(fmaf(f0.x, s0.x, s0.y), 0.f),
                                       fmaxf(fmaf(f0.y, s1.x, s1.y), 0.f));
                afrag[im][1] = pack_h2(fmaxf(fmaf(f1.x, s0.x, s0.y), 0.f),
                                       fmaxf(fmaf(f1.y, s1.x, s1.y), 0.f));
                afrag[im][2] = pack_h2(fmaxf(fmaf(f2.x, s2.x, s2.y), 0.f),
                                       fmaxf(fmaf(f2.y, s3.x, s3.y), 0.f));
                afrag[im][3] = pack_h2(fmaxf(fmaf(f3.x, s2.x, s2.y), 0.f),
                                       fmaxf(fmaf(f3.y, s3.x, s3.y), 0.f));
            }
#pragma unroll
            for (int jp = 0; jp < 4; jp++)
                ldsm_x4(bfrag[2*jp][0], bfrag[2*jp][1], bfrag[2*jp+1][0], bfrag[2*jp+1][1],
                        pb + (warpN * 64 + jp * 16 + b_r) * HASTR + kk + b_c);
#pragma unroll
            for (int im = 0; im < 2; im++)
#pragma unroll
                for (int jn = 0; jn < 8; jn++) {
                    float4& c = acc[im][jn];
                    asm volatile(
                        "mma.sync.aligned.m16n8k16.row.col.f32.f16.f16.f32 "
                        "{%0,%1,%2,%3}, {%4,%5,%6,%7}, {%8,%9}, {%0,%1,%2,%3};"
                        : "+f"(c.x), "+f"(c.y), "+f"(c.z), "+f"(c.w)
                        : "r"(afrag[im][0]), "r"(afrag[im][1]),
                          "r"(afrag[im][2]), "r"(afrag[im][3]),
                          "r"(bfrag[jn][0]), "r"(bfrag[jn][1]));
                }
        }
        __syncthreads();
    }

#pragma unroll
    for (int jn = 0; jn < 8; jn++) {
        int col = bn + warpN * 64 + jn * 8 + 2 * t;
        float bx = bias[col], by = bias[col + 1];
#pragma unroll
        for (int im = 0; im < 2; im++) {
            int row0 = bm + warpM * 32 + im * 16 + g;
            float4 c = acc[im][jn];
            if (row0 < M)
                *(float2*)(C + (size_t)row0 * N + col) = make_float2(c.x + bx, c.y + by);
            if (row0 + 8 < M)
                *(float2*)(C + (size_t)(row0 + 8) * N + col) = make_float2(c.z + bx, c.w + by);
        }
    }
}

// --- stats -> per-col (scale, shift) ------------------------------------------
__global__ void k_bnprep(const float2* __restrict__ stats,
                         const float* __restrict__ gamma,
                         const float* __restrict__ beta,
                         float2* __restrict__ ss, int D, float invM) {
    int c = blockIdx.x * blockDim.x + threadIdx.x;
    if (c < D) {
        float mu = stats[c].x * invM;
        float var = stats[c].y * invM - mu * mu;
        float sc = gamma[c] * rsqrtf(var + EPS);
        ss[c] = make_float2(sc, beta[c] - mu * sc);
    }
}

// ---------------------------------------------------------------------------

extern "C" void kernel_launch(void* const* d_in, const int* in_sizes, int n_in,
                              void* d_out, int out_size) {
    const float* x      = (const float*)d_in[0];
    const void*  ei     = d_in[1];
    const float* W1     = (const float*)d_in[2];
    const float* b1     = (const float*)d_in[3];
    const float* gamma1 = (const float*)d_in[4];
    const float* beta1  = (const float*)d_in[5];
    const float* W2     = (const float*)d_in[6];
    const float* b2     = (const float*)d_in[7];
    const float* gamma2 = (const float*)d_in[8];
    const float* beta2  = (const float*)d_in[9];
    const float* Wl     = (const float*)d_in[10];
    const float* bl     = (const float*)d_in[11];

    const int H1   = in_sizes[3];
    const int H2   = in_sizes[7];
    const int DOUT = in_sizes[11];
    const int DIN  = in_sizes[2] / H1;
    const int N    = in_sizes[0] / DIN;
    const long long E = in_sizes[1] / 2;
    const float invM = 1.0f / (float)N;

    float *dinv;
    __half *agg1h, *agg2h, *h1, *h2, *w1t, *w2t, *wlt;
    float2 *stats1, *stats2, *ss1, *ss2;
    int *cnt, *rowptr, *cursor, *flag, *bsum;
    int2* adj;
    cudaGetSymbolAddress((void**)&dinv,   g_dinv);
    cudaGetSymbolAddress((void**)&cnt,    g_cnt);
    cudaGetSymbolAddress((void**)&rowptr, g_rowptr);
    cudaGetSymbolAddress((void**)&cursor, g_cursor);
    cudaGetSymbolAddress((void**)&bsum,   g_bsum);
    cudaGetSymbolAddress((void**)&adj,    g_adj);
    cudaGetSymbolAddress((void**)&agg1h,  g_agg1h);
    cudaGetSymbolAddress((void**)&agg2h,  g_agg2h);
    cudaGetSymbolAddress((void**)&h1,     g_h1);
    cudaGetSymbolAddress((void**)&h2,     g_h2);
    cudaGetSymbolAddress((void**)&w1t,    g_w1t);
    cudaGetSymbolAddress((void**)&w2t,    g_w2t);
    cudaGetSymbolAddress((void**)&wlt,    g_wlt);
    cudaGetSymbolAddress((void**)&stats1, g_stats1);
    cudaGetSymbolAddress((void**)&stats2, g_stats2);
    cudaGetSymbolAddress((void**)&ss1,    g_ss1);
    cudaGetSymbolAddress((void**)&ss2,    g_ss2);
    cudaGetSymbolAddress((void**)&flag,   g_flag32);

    float* out = (float*)d_out;

    cudaFuncSetAttribute(k_gemm_h,    cudaFuncAttributeMaxDynamicSharedMemorySize, SMEM_H);
    cudaFuncSetAttribute(k_gemm_finh, cudaFuncAttributeMaxDynamicSharedMemorySize, SMEM_FINH);

    const int scanBlocks = (N + SCAN_BLK - 1) / SCAN_BLK;
    const int aggBlocks = (int)(((long long)N * 32 + 255) / 256);

    // prep (5 launches) -> agg1 is launch #6
    k_prep0<<<(N + 255) / 256, 256>>>((const int*)ei, E, cnt, N, stats1, stats2, H1, H2, flag);
    k_count<<<1024, 256>>>(ei, E, flag, cnt);
    k_scan_red<<<scanBlocks, SCAN_BLK>>>(cnt, bsum, N);
    k_scan_apply<<<scanBlocks, SCAN_BLK>>>(cnt, bsum, scanBlocks, rowptr, cursor, dinv, N);
    k_fill<<<1024, 256>>>(ei, E, flag, dinv, cursor, adj);

    k_agg1<<<aggBlocks, 256>>>(adj, rowptr, dinv, x, agg1h, N);

    k_cvtw<<<(H1 * H2 + 255) / 256, 256>>>(W1, W2, Wl, w1t, w2t, wlt,
                                           DIN, H1, H1, H2, H2, DOUT);

    {
        dim3 grid(H1 / GBN, (N + GBM - 1) / GBM);
        k_gemm_h<<<grid, 256, SMEM_H>>>(agg1h, w1t, b1, h1, stats1, N, H1, DIN);
        k_bnprep<<<(H1 + 255) / 256, 256>>>(stats1, gamma1, beta1, ss1, H1, invM);
    }

    k_agg2<<<aggBlocks, 256>>>(adj, rowptr, dinv, h1, agg2h, N, ss1);
    {
        dim3 grid(H2 / GBN, (N + GBM - 1) / GBM);
        k_gemm_h<<<grid, 256, SMEM_H>>>(agg2h, w2t, b2, h2, stats2, N, H2, H1);
        k_bnprep<<<(H2 + 255) / 256, 256>>>(stats2, gamma2, beta2, ss2, H2, invM);
    }

    {
        dim3 grid(DOUT / GBN, (N + GBM - 1) / GBM);
        k_gemm_finh<<<grid, 256, SMEM_FINH>>>(h2, wlt, bl, out, ss2, N, DOUT, H2);
    }
}

// round 9
// speedup vs baseline: 1.0121x; 1.0121x over previous
#include <cuda_runtime.h>
#include <cuda_bf16.h>
#include <cuda_fp16.h>
#include <cstdint>

// ---------------------------------------------------------------------------
// GCN encoder: N=50000, E=500000, 128 -> 256 -> 512 -> 128
// CSR gather aggregation (fp16 gathers both layers, BN fused)
// + fp16 tensor-core GEMM pipelines (round-7 proven core)
// ---------------------------------------------------------------------------

#define MAXN 50048
#define MAXE 524288
#define EPS 1e-5f
#define SCAN_BLK 1024

__device__ float  g_dinv[MAXN];
__device__ int    g_cnt[MAXN];
__device__ int    g_rowptr[MAXN + 1];
__device__ int    g_cursor[MAXN];
__device__ int    g_bsum[64];
__device__ int2   g_adj[MAXE];                 // (src, bits(w))
__device__ __half g_xh[(size_t)MAXN * 128];    // fp16 copy of x
__device__ __half g_agg1h[(size_t)MAXN * 128];
__device__ __half g_agg2h[(size_t)MAXN * 256];
__device__ __half g_h1[(size_t)MAXN * 256];    // fp16 raw (pre-BN)
__device__ __half g_h2[(size_t)MAXN * 512];
__device__ __half g_w1t[256 * 128];            // fp16 W1^T [N][K]
__device__ __half g_w2t[512 * 256];
__device__ __half g_wlt[128 * 512];
__device__ float2 g_stats1[256];
__device__ float2 g_stats2[512];
__device__ float2 g_ss1[256];
__device__ float2 g_ss2[512];
__device__ int    g_flag32;

// ---------------------------------------------------------------------------

__device__ __forceinline__ void red_add_v2(float2* addr, float a, float b) {
    asm volatile("red.global.add.v2.f32 [%0], {%1,%2};"
                 :: "l"(addr), "f"(a), "f"(b) : "memory");
}

__device__ __forceinline__ int load_idx(const void* ei, long long pos, int is32) {
    if (is32) return ((const int*)ei)[pos];
    return (int)(((const long long*)ei)[pos]);
}

__device__ __forceinline__ uint32_t pack_h2(float lo, float hi) {
    uint32_t u;
    asm("cvt.rn.f16x2.f32 %0, %1, %2;" : "=r"(u) : "f"(hi), "f"(lo));
    return u;
}

__device__ __forceinline__ float2 unpack_h2(uint32_t u) {
    __half2 h = *(__half2*)&u;
    return __half22float2(h);
}

__device__ __forceinline__ void cp_async16(void* sptr, const void* gptr, int src_bytes) {
    uint32_t sa = (uint32_t)__cvta_generic_to_shared(sptr);
    asm volatile("cp.async.cg.shared.global [%0], [%1], 16, %2;"
                 :: "r"(sa), "l"(gptr), "r"(src_bytes));
}

// --- prep0 (+fused dtype detect on block 0): zero cnt + stats ----------------
__global__ void k_prep0(const int* __restrict__ ei32, long long E,
                        int* cnt, int n, float2* st1, float2* st2,
                        int d1, int d2, int* flag) {
    int i = blockIdx.x * blockDim.x + threadIdx.x;
    if (blockIdx.x == 0) {
        long long lim = E < 8192 ? E : 8192;
        int any = 0;
        for (long long j = threadIdx.x; j < lim; j += blockDim.x)
            if (ei32[2 * j + 1] != 0) any = 1;
        if (any) atomicOr(flag, 1);
    }
    if (i < n) cnt[i] = 0;
    if (i < d1) st1[i] = make_float2(0.f, 0.f);
    if (i < d2) st2[i] = make_float2(0.f, 0.f);
}

// --- x -> fp16 copy -------------------------------------------------------------
__global__ void k_cvtx(const float* __restrict__ X, __half* __restrict__ Xh,
                       long long n2) {
    long long i = blockIdx.x * (long long)blockDim.x + threadIdx.x;
    long long stride = (long long)gridDim.x * blockDim.x;
    for (; i < n2; i += stride) {
        float2 v = ((const float2*)X)[i];
        ((uint32_t*)Xh)[i] = pack_h2(v.x, v.y);
    }
}

// --- in-degree counts ---------------------------------------------------------
__global__ void k_count(const void* ei, long long E, const int* flag, int* cnt) {
    long long i = blockIdx.x * (long long)blockDim.x + threadIdx.x;
    long long stride = (long long)gridDim.x * blockDim.x;
    int is32 = *flag;
    for (; i < E; i += stride) {
        int d = load_idx(ei, E + i, is32);
        atomicAdd(&cnt[d], 1);
    }
}

// --- scan pass 1: per-block sums -----------------------------------------------
__global__ __launch_bounds__(SCAN_BLK) void k_scan_red(const int* __restrict__ cnt,
                                                       int* __restrict__ bsum, int n) {
    int i = blockIdx.x * SCAN_BLK + threadIdx.x;
    int v = (i < n) ? cnt[i] : 0;
    int lane = threadIdx.x & 31, wid = threadIdx.x >> 5;
#pragma unroll
    for (int off = 16; off; off >>= 1) v += __shfl_xor_sync(0xffffffffu, v, off);
    __shared__ int ws[32];
    if (lane == 0) ws[wid] = v;
    __syncthreads();
    if (wid == 0) {
        v = ws[lane];
#pragma unroll
        for (int off = 16; off; off >>= 1) v += __shfl_xor_sync(0xffffffffu, v, off);
        if (lane == 0) bsum[blockIdx.x] = v;
    }
}

// --- scan pass 2: block offset + local scan + apply -----------------------------
__global__ __launch_bounds__(SCAN_BLK) void k_scan_apply(const int* __restrict__ cnt,
                                                         const int* __restrict__ bsum, int nb,
                                                         int* __restrict__ rowptr,
                                                         int* __restrict__ cursor,
                                                         float* __restrict__ dinv, int n) {
    int tid = threadIdx.x;
    int lane = tid & 31, wid = tid >> 5;
    __shared__ int ws[32];
    __shared__ int s_off;

    int b = (tid < nb && tid < blockIdx.x) ? bsum[tid] : 0;
#pragma unroll
    for (int off = 16; off; off >>= 1) b += __shfl_xor_sync(0xffffffffu, b, off);
    if (lane == 0) ws[wid] = b;
    __syncthreads();
    if (wid == 0) {
        int w = ws[lane];
#pragma unroll
        for (int off = 16; off; off >>= 1) w += __shfl_xor_sync(0xffffffffu, w, off);
        if (lane == 0) s_off = w;
    }
    __syncthreads();
    int offset = s_off;
    __syncthreads();

    int i = blockIdx.x * SCAN_BLK + tid;
    int v = (i < n) ? cnt[i] : 0;
    int x = v;
#pragma unroll
    for (int off = 1; off < 32; off <<= 1) {
        int y = __shfl_up_sync(0xffffffffu, x, off);
        if (lane >= off) x += y;
    }
    if (lane == 31) ws[wid] = x;
    __syncthreads();
    if (wid == 0) {
        int w = ws[lane];
#pragma unroll
        for (int off = 1; off < 32; off <<= 1) {
            int y = __shfl_up_sync(0xffffffffu, w, off);
            if (lane >= off) w += y;
        }
        ws[lane] = w;
    }
    __syncthreads();
    int incl = x + (wid > 0 ? ws[wid - 1] : 0);
    int excl = incl - v + offset;
    if (i < n) {
        rowptr[i] = excl;
        cursor[i] = excl;
        dinv[i] = rsqrtf((float)v + 1.0f);
        if (i == n - 1) rowptr[n] = excl + v;
    }
}

// --- bucket-fill adjacency -------------------------------------------------------
__global__ void k_fill(const void* __restrict__ ei, long long E, const int* flag,
                       const float* __restrict__ dinv, int* __restrict__ cursor,
                       int2* __restrict__ adj) {
    long long i = blockIdx.x * (long long)blockDim.x + threadIdx.x;
    long long stride = (long long)gridDim.x * blockDim.x;
    int is32 = *flag;
    for (; i < E; i += stride) {
        int s = load_idx(ei, i, is32);
        int d = load_idx(ei, E + i, is32);
        float w = dinv[s] * dinv[d];
        int pos = atomicAdd(&cursor[d], 1);
        adj[pos] = make_int2(s, __float_as_int(w));
    }
}

// --- weight convert: all three -> fp16 transposed [N][K] --------------------------
__global__ void k_cvtw(const float* __restrict__ W1, const float* __restrict__ W2,
                       const float* __restrict__ W3,
                       __half* __restrict__ t1, __half* __restrict__ t2,
                       __half* __restrict__ t3,
                       int K1, int N1, int K2, int N2, int K3, int N3) {
    int i = blockIdx.x * blockDim.x + threadIdx.x;
    if (i < K1 * N1) {
        int k = i / N1, n = i % N1;
        t1[n * K1 + k] = __float2half_rn(W1[i]);
    }
    if (i < K2 * N2) {
        int k = i / N2, n = i % N2;
        t2[n * K2 + k] = __float2half_rn(W2[i]);
    }
    if (i < K3 * N3) {
        int k = i / N3, n = i % N3;
        t3[n * K3 + k] = __float2half_rn(W3[i]);
    }
}

// --- agg layer 1: fp16 x in, fp16 out (no BN), prefetch loop ----------------------
__global__ __launch_bounds__(256) void k_agg1(const int2* __restrict__ adj,
                                              const int* __restrict__ rowptr,
                                              const float* __restrict__ dinv,
                                              const __half* __restrict__ Xh,
                                              __half* __restrict__ out, int N) {
    int node = (blockIdx.x * blockDim.x + threadIdx.x) >> 5;
    int lane = threadIdx.x & 31;
    if (node >= N) return;
    float w0 = dinv[node]; w0 *= w0;
    float4 acc;
    {
        uint2 u = ((const uint2*)(Xh + (size_t)node * 128))[lane];
        float2 f0 = unpack_h2(u.x), f1 = unpack_h2(u.y);
        acc = make_float4(f0.x * w0, f0.y * w0, f1.x * w0, f1.y * w0);
    }
    int j = rowptr[node], end = rowptr[node + 1];
    int2 e = (j < end) ? adj[j] : make_int2(0, 0);
    for (; j < end; j++) {
        int2 cur = e;
        if (j + 1 < end) e = adj[j + 1];
        float w = __int_as_float(cur.y);
        uint2 u = ((const uint2*)(Xh + (size_t)cur.x * 128))[lane];
        float2 f0 = unpack_h2(u.x), f1 = unpack_h2(u.y);
        acc.x += w * f0.x; acc.y += w * f0.y;
        acc.z += w * f1.x; acc.w += w * f1.y;
    }
    ((uint2*)(out + (size_t)node * 128))[lane] =
        make_uint2(pack_h2(acc.x, acc.y), pack_h2(acc.z, acc.w));
}

// --- agg layer 2: fp16 h1 in (BN+ReLU fused), fp16 out, prefetch loop -------------
__global__ __launch_bounds__(256) void k_agg2(const int2* __restrict__ adj,
                                              const int* __restrict__ rowptr,
                                              const float* __restrict__ dinv,
                                              const __half* __restrict__ X,
                                              __half* __restrict__ out, int N,
                                              const float2* __restrict__ ss) {
    int node = (blockIdx.x * blockDim.x + threadIdx.x) >> 5;
    int lane = threadIdx.x & 31;
    if (node >= N) return;
    float2 sr[8];
#pragma unroll
    for (int j = 0; j < 8; j++) sr[j] = ss[lane * 8 + j];

    float acc[8];
    float w0 = dinv[node]; w0 *= w0;
    {
        uint4 u = ((const uint4*)(X + (size_t)node * 256))[lane];
        float2 f0 = unpack_h2(u.x), f1 = unpack_h2(u.y);
        float2 f2 = unpack_h2(u.z), f3 = unpack_h2(u.w);
        float f[8] = {f0.x, f0.y, f1.x, f1.y, f2.x, f2.y, f3.x, f3.y};
#pragma unroll
        for (int j = 0; j < 8; j++)
            acc[j] = w0 * fmaxf(fmaf(f[j], sr[j].x, sr[j].y), 0.f);
    }
    int j = rowptr[node], end = rowptr[node + 1];
    int2 e = (j < end) ? adj[j] : make_int2(0, 0);
    for (; j < end; j++) {
        int2 cur = e;
        if (j + 1 < end) e = adj[j + 1];
        float w = __int_as_float(cur.y);
        uint4 u = ((const uint4*)(X + (size_t)cur.x * 256))[lane];
        float2 f0 = unpack_h2(u.x), f1 = unpack_h2(u.y);
        float2 f2 = unpack_h2(u.z), f3 = unpack_h2(u.w);
        float f[8] = {f0.x, f0.y, f1.x, f1.y, f2.x, f2.y, f3.x, f3.y};
#pragma unroll
        for (int jj = 0; jj < 8; jj++)
            acc[jj] += w * fmaxf(fmaf(f[jj], sr[jj].x, sr[jj].y), 0.f);
    }
    uint4 o;
    o.x = pack_h2(acc[0], acc[1]);
    o.y = pack_h2(acc[2], acc[3]);
    o.z = pack_h2(acc[4], acc[5]);
    o.w = pack_h2(acc[6], acc[7]);
    ((uint4*)(out + (size_t)node * 256))[lane] = o;
}

// ---------------------------------------------------------------------------
// fp16 pipelined GEMM (round-7 core): LDS.32 frag loads, cp.async 2-stage,
// block 128x128, 8 warps, BK=32. C fp16 + fused fp32 BN stats.
// ---------------------------------------------------------------------------
#define GBM 128
#define GBN 128
#define HASTR 40
#define HTSZ (128 * HASTR)
#define SMEM_H ((4 * HTSZ) * 2)
#define SMEM_FINH (SMEM_H + 512 * 8)

__global__ __launch_bounds__(256) void k_gemm_h(const __half* __restrict__ A,
                                                const __half* __restrict__ Bt,
                                                const float* __restrict__ bias,
                                                __half* __restrict__ C,
                                                float2* __restrict__ stats,
                                                int M, int N, int K) {
    extern __shared__ __half smh[];
    __half* As = smh;
    __half* Bs = smh + 2 * HTSZ;

    const int tid  = threadIdx.x;
    const int lane = tid & 31;
    const int warpId = tid >> 5;
    const int warpM = warpId & 3;
    const int warpN = warpId >> 2;
    const int g = lane >> 2;
    const int t = lane & 3;
    const int bm = blockIdx.y * GBM;
    const int bn = blockIdx.x * GBN;

    const int l_row = tid >> 2;
    const int l_chk = (tid & 3) * 8;

    float4 acc[2][8];
#pragma unroll
    for (int i = 0; i < 2; i++)
#pragma unroll
        for (int j = 0; j < 8; j++)
            acc[i][j] = make_float4(0.f, 0.f, 0.f, 0.f);

    auto load_stage = [&](int stg, int k0) {
        __half* pa = As + stg * HTSZ;
        __half* pb = Bs + stg * HTSZ;
#pragma unroll
        for (int i = 0; i < 2; i++) {
            int row = i * 64 + l_row;
            int gm = bm + row;
            int ok = (gm < M) ? 16 : 0;
            int gmc = min(gm, M - 1);
            cp_async16(pa + row * HASTR + l_chk, A + (size_t)gmc * K + k0 + l_chk, ok);
        }
#pragma unroll
        for (int i = 0; i < 2; i++) {
            int row = i * 64 + l_row;
            cp_async16(pb + row * HASTR + l_chk, Bt + (size_t)(bn + row) * K + k0 + l_chk, 16);
        }
    };

    const int nk = K / 32;
    load_stage(0, 0);
    asm volatile("cp.async.commit_group;");

    for (int tk = 0; tk < nk; tk++) {
        if (tk + 1 < nk) {
            load_stage((tk + 1) & 1, (tk + 1) * 32);
            asm volatile("cp.async.commit_group;");
            asm volatile("cp.async.wait_group 1;");
        } else {
            asm volatile("cp.async.wait_group 0;");
        }
        __syncthreads();

        const __half* pa = As + (tk & 1) * HTSZ;
        const __half* pb = Bs + (tk & 1) * HTSZ;
#pragma unroll
        for (int kk = 0; kk < 32; kk += 16) {
            uint32_t afrag[2][4];
            uint32_t bfrag[8][2];
#pragma unroll
            for (int im = 0; im < 2; im++) {
                const __half* base = pa + (warpM * 32 + im * 16 + g) * HASTR + kk + 2 * t;
                afrag[im][0] = *(const uint32_t*)(base);
                afrag[im][1] = *(const uint32_t*)(base + 8 * HASTR);
                afrag[im][2] = *(const uint32_t*)(base + 8);
                afrag[im][3] = *(const uint32_t*)(base + 8 * HASTR + 8);
            }
#pragma unroll
            for (int jn = 0; jn < 8; jn++) {
                const __half* base = pb + (warpN * 64 + jn * 8 + g) * HASTR + kk + 2 * t;
                bfrag[jn][0] = *(const uint32_t*)(base);
                bfrag[jn][1] = *(const uint32_t*)(base + 8);
            }
#pragma unroll
            for (int im = 0; im < 2; im++)
#pragma unroll
                for (int jn = 0; jn < 8; jn++) {
                    float4& c = acc[im][jn];
                    asm volatile(
                        "mma.sync.aligned.m16n8k16.row.col.f32.f16.f16.f32 "
                        "{%0,%1,%2,%3}, {%4,%5,%6,%7}, {%8,%9}, {%0,%1,%2,%3};"
                        : "+f"(c.x), "+f"(c.y), "+f"(c.z), "+f"(c.w)
                        : "r"(afrag[im][0]), "r"(afrag[im][1]),
                          "r"(afrag[im][2]), "r"(afrag[im][3]),
                          "r"(bfrag[jn][0]), "r"(bfrag[jn][1]));
                }
        }
        __syncthreads();
    }

#pragma unroll
    for (int jn = 0; jn < 8; jn++) {
        int col = bn + warpN * 64 + jn * 8 + 2 * t;
        float bx = bias[col], by = bias[col + 1];
        float s0 = 0.f, q0 = 0.f, s1 = 0.f, q1 = 0.f;
#pragma unroll
        for (int im = 0; im < 2; im++) {
            int row0 = bm + warpM * 32 + im * 16 + g;
            float4 c = acc[im][jn];
            if (row0 < M) {
                float ox = c.x + bx, oy = c.y + by;
                *(uint32_t*)(C + (size_t)row0 * N + col) = pack_h2(ox, oy);
                s0 += ox; q0 += ox * ox; s1 += oy; q1 += oy * oy;
            }
            if (row0 + 8 < M) {
                float oz = c.z + bx, ow = c.w + by;
                *(uint32_t*)(C + (size_t)(row0 + 8) * N + col) = pack_h2(oz, ow);
                s0 += oz; q0 += oz * oz; s1 += ow; q1 += ow * ow;
            }
        }
#pragma unroll
        for (int m = 4; m < 32; m <<= 1) {
            s0 += __shfl_xor_sync(0xffffffffu, s0, m);
            q0 += __shfl_xor_sync(0xffffffffu, q0, m);
            s1 += __shfl_xor_sync(0xffffffffu, s1, m);
            q1 += __shfl_xor_sync(0xffffffffu, q1, m);
        }
        if (g == 0) {
            red_add_v2(&stats[col], s0, q0);
            red_add_v2(&stats[col + 1], s1, q1);
        }
    }
}

// ---------------------------------------------------------------------------
// Final fp16 GEMM (round-7 core): BN2+ReLU applied at frag build, fp32 out.
// ---------------------------------------------------------------------------
__global__ __launch_bounds__(256) void k_gemm_finh(const __half* __restrict__ A,
                                                   const __half* __restrict__ Bt,
                                                   const float* __restrict__ bias,
                                                   float* __restrict__ C,
                                                   const float2* __restrict__ ssA,
                                                   int M, int N, int K) {
    extern __shared__ __half smh[];
    __half* As = smh;
    __half* Bs = smh + 2 * HTSZ;
    float2* ssm = (float2*)(smh + 4 * HTSZ);

    const int tid  = threadIdx.x;
    const int lane = tid & 31;
    const int warpId = tid >> 5;
    const int warpM = warpId & 3;
    const int warpN = warpId >> 2;
    const int g = lane >> 2;
    const int t = lane & 3;
    const int bm = blockIdx.y * GBM;
    const int bn = blockIdx.x * GBN;

    for (int c = tid; c < K; c += 256) ssm[c] = ssA[c];

    const int l_row = tid >> 2;
    const int l_chk = (tid & 3) * 8;

    float4 acc[2][8];
#pragma unroll
    for (int i = 0; i < 2; i++)
#pragma unroll
        for (int j = 0; j < 8; j++)
            acc[i][j] = make_float4(0.f, 0.f, 0.f, 0.f);

    auto load_stage = [&](int stg, int k0) {
        __half* pa = As + stg * HTSZ;
        __half* pb = Bs + stg * HTSZ;
#pragma unroll
        for (int i = 0; i < 2; i++) {
            int row = i * 64 + l_row;
            int gm = bm + row;
            int ok = (gm < M) ? 16 : 0;
            int gmc = min(gm, M - 1);
            cp_async16(pa + row * HASTR + l_chk, A + (size_t)gmc * K + k0 + l_chk, ok);
        }
#pragma unroll
        for (int i = 0; i < 2; i++) {
            int row = i * 64 + l_row;
            cp_async16(pb + row * HASTR + l_chk, Bt + (size_t)(bn + row) * K + k0 + l_chk, 16);
        }
    };

    const int nk = K / 32;
    load_stage(0, 0);
    asm volatile("cp.async.commit_group;");

    for (int tk = 0; tk < nk; tk++) {
        if (tk + 1 < nk) {
            load_stage((tk + 1) & 1, (tk + 1) * 32);
            asm volatile("cp.async.commit_group;");
            asm volatile("cp.async.wait_group 1;");
        } else {
            asm volatile("cp.async.wait_group 0;");
        }
        __syncthreads();

        const __half* pa = As + (tk & 1) * HTSZ;
        const __half* pb = Bs + (tk & 1) * HTSZ;
        const int kbase = tk * 32;
#pragma unroll
        for (int kk = 0; kk < 32; kk += 16) {
            int kc = kbase + kk + 2 * t;
            float2 s0 = ssm[kc],     s1 = ssm[kc + 1];
            float2 s2 = ssm[kc + 8], s3 = ssm[kc + 9];
            uint32_t afrag[2][4];
            uint32_t bfrag[8][2];
#pragma unroll
            for (int im = 0; im < 2; im++) {
                const __half* base = pa + (warpM * 32 + im * 16 + g) * HASTR + kk + 2 * t;
                float2 f0 = unpack_h2(*(const uint32_t*)(base));
                float2 f1 = unpack_h2(*(const uint32_t*)(base + 8 * HASTR));
                float2 f2 = unpack_h2(*(const uint32_t*)(base + 8));
                float2 f3 = unpack_h2(*(const uint32_t*)(base + 8 * HASTR + 8));
                afrag[im][0] = pack_h2(fmaxf(fmaf(f0.x, s0.x, s0.y), 0.f),
                                       fmaxf(fmaf(f0.y, s1.x, s1.y), 0.f));
                afrag[im][1] = pack_h2(fmaxf(fmaf(f1.x, s0.x, s0.y), 0.f),
                                       fmaxf(fmaf(f1.y, s1.x, s1.y), 0.f));
                afrag[im][2] = pack_h2(fmaxf(fmaf(f2.x, s2.x, s2.y), 0.f),
                                       fmaxf(fmaf(f2.y, s3.x, s3.y), 0.f));
                afrag[im][3] = pack_h2(fmaxf(fmaf(f3.x, s2.x, s2.y), 0.f),
                                       fmaxf(fmaf(f3.y, s3.x, s3.y), 0.f));
            }
#pragma unroll
            for (int jn = 0; jn < 8; jn++) {
                const __half* base = pb + (warpN * 64 + jn * 8 + g) * HASTR + kk + 2 * t;
                bfrag[jn][0] = *(const uint32_t*)(base);
                bfrag[jn][1] = *(const uint32_t*)(base + 8);
            }
#pragma unroll
            for (int im = 0; im < 2; im++)
#pragma unroll
                for (int jn = 0; jn < 8; jn++) {
                    float4& c = acc[im][jn];
                    asm volatile(
                        "mma.sync.aligned.m16n8k16.row.col.f32.f16.f16.f32 "
                        "{%0,%1,%2,%3}, {%4,%5,%6,%7}, {%8,%9}, {%0,%1,%2,%3};"
                        : "+f"(c.x), "+f"(c.y), "+f"(c.z), "+f"(c.w)
                        : "r"(afrag[im][0]), "r"(afrag[im][1]),
                          "r"(afrag[im][2]), "r"(afrag[im][3]),
                          "r"(bfrag[jn][0]), "r"(bfrag[jn][1]));
                }
        }
        __syncthreads();
    }

#pragma unroll
    for (int jn = 0; jn < 8; jn++) {
        int col = bn + warpN * 64 + jn * 8 + 2 * t;
        float bx = bias[col], by = bias[col + 1];
#pragma unroll
        for (int im = 0; im < 2; im++) {
            int row0 = bm + warpM * 32 + im * 16 + g;
            float4 c = acc[im][jn];
            if (row0 < M)
                *(float2*)(C + (size_t)row0 * N + col) = make_float2(c.x + bx, c.y + by);
            if (row0 + 8 < M)
                *(float2*)(C + (size_t)(row0 + 8) * N + col) = make_float2(c.z + bx, c.w + by);
        }
    }
}

// --- stats -> per-col (scale, shift) ------------------------------------------
__global__ void k_bnprep(const float2* __restrict__ stats,
                         const float* __restrict__ gamma,
                         const float* __restrict__ beta,
                         float2* __restrict__ ss, int D, float invM) {
    int c = blockIdx.x * blockDim.x + threadIdx.x;
    if (c < D) {
        float mu = stats[c].x * invM;
        float var = stats[c].y * invM - mu * mu;
        float sc = gamma[c] * rsqrtf(var + EPS);
        ss[c] = make_float2(sc, beta[c] - mu * sc);
    }
}

// ---------------------------------------------------------------------------

extern "C" void kernel_launch(void* const* d_in, const int* in_sizes, int n_in,
                              void* d_out, int out_size) {
    const float* x      = (const float*)d_in[0];
    const void*  ei     = d_in[1];
    const float* W1     = (const float*)d_in[2];
    const float* b1     = (const float*)d_in[3];
    const float* gamma1 = (const float*)d_in[4];
    const float* beta1  = (const float*)d_in[5];
    const float* W2     = (const float*)d_in[6];
    const float* b2     = (const float*)d_in[7];
    const float* gamma2 = (const float*)d_in[8];
    const float* beta2  = (const float*)d_in[9];
    const float* Wl     = (const float*)d_in[10];
    const float* bl     = (const float*)d_in[11];

    const int H1   = in_sizes[3];
    const int H2   = in_sizes[7];
    const int DOUT = in_sizes[11];
    const int DIN  = in_sizes[2] / H1;
    const int N    = in_sizes[0] / DIN;
    const long long E = in_sizes[1] / 2;
    const float invM = 1.0f / (float)N;

    float *dinv;
    __half *xh, *agg1h, *agg2h, *h1, *h2, *w1t, *w2t, *wlt;
    float2 *stats1, *stats2, *ss1, *ss2;
    int *cnt, *rowptr, *cursor, *flag, *bsum;
    int2* adj;
    cudaGetSymbolAddress((void**)&dinv,   g_dinv);
    cudaGetSymbolAddress((void**)&cnt,    g_cnt);
    cudaGetSymbolAddress((void**)&rowptr, g_rowptr);
    cudaGetSymbolAddress((void**)&cursor, g_cursor);
    cudaGetSymbolAddress((void**)&bsum,   g_bsum);
    cudaGetSymbolAddress((void**)&adj,    g_adj);
    cudaGetSymbolAddress((void**)&xh,     g_xh);
    cudaGetSymbolAddress((void**)&agg1h,  g_agg1h);
    cudaGetSymbolAddress((void**)&agg2h,  g_agg2h);
    cudaGetSymbolAddress((void**)&h1,     g_h1);
    cudaGetSymbolAddress((void**)&h2,     g_h2);
    cudaGetSymbolAddress((void**)&w1t,    g_w1t);
    cudaGetSymbolAddress((void**)&w2t,    g_w2t);
    cudaGetSymbolAddress((void**)&wlt,    g_wlt);
    cudaGetSymbolAddress((void**)&stats1, g_stats1);
    cudaGetSymbolAddress((void**)&stats2, g_stats2);
    cudaGetSymbolAddress((void**)&ss1,    g_ss1);
    cudaGetSymbolAddress((void**)&ss2,    g_ss2);
    cudaGetSymbolAddress((void**)&flag,   g_flag32);

    float* out = (float*)d_out;

    cudaFuncSetAttribute(k_gemm_h,    cudaFuncAttributeMaxDynamicSharedMemorySize, SMEM_H);
    cudaFuncSetAttribute(k_gemm_finh, cudaFuncAttributeMaxDynamicSharedMemorySize, SMEM_FINH);

    const int scanBlocks = (N + SCAN_BLK - 1) / SCAN_BLK;
    const int aggBlocks = (int)(((long long)N * 32 + 255) / 256);

    // prep
    k_prep0<<<(N + 255) / 256, 256>>>((const int*)ei, E, cnt, N, stats1, stats2, H1, H2, flag);
    k_cvtx<<<512, 256>>>(x, xh, (long long)N * DIN / 2);
    k_count<<<1024, 256>>>(ei, E, flag, cnt);
    k_scan_red<<<scanBlocks, SCAN_BLK>>>(cnt, bsum, N);
    k_scan_apply<<<scanBlocks, SCAN_BLK>>>(cnt, bsum, scanBlocks, rowptr, cursor, dinv, N);
    k_fill<<<1024, 256>>>(ei, E, flag, dinv, cursor, adj);

    // layer 1 aggregation (fp16 gather)
    k_agg1<<<aggBlocks, 256>>>(adj, rowptr, dinv, xh, agg1h, N);

    k_cvtw<<<(H1 * H2 + 255) / 256, 256>>>(W1, W2, Wl, w1t, w2t, wlt,
                                           DIN, H1, H1, H2, H2, DOUT);

    {
        dim3 grid(H1 / GBN, (N + GBM - 1) / GBM);
        k_gemm_h<<<grid, 256, SMEM_H>>>(agg1h, w1t, b1, h1, stats1, N, H1, DIN);
        k_bnprep<<<(H1 + 255) / 256, 256>>>(stats1, gamma1, beta1, ss1, H1, invM);
    }

    k_agg2<<<aggBlocks, 256>>>(adj, rowptr, dinv, h1, agg2h, N, ss1);
    {
        dim3 grid(H2 / GBN, (N + GBM - 1) / GBM);
        k_gemm_h<<<grid, 256, SMEM_H>>>(agg2h, w2t, b2, h2, stats2, N, H2, H1);
        k_bnprep<<<(H2 + 255) / 256, 256>>>(stats2, gamma2, beta2, ss2, H2, invM);
    }

    {
        dim3 grid(DOUT / GBN, (N + GBM - 1) / GBM);
        k_gemm_finh<<<grid, 256, SMEM_FINH>>>(h2, wlt, bl, out, ss2, N, DOUT, H2);
    }
}

// round 11
// speedup vs baseline: 1.0122x; 1.0001x over previous
#include <cuda_runtime.h>
#include <cuda_bf16.h>
#include <cuda_fp16.h>
#include <cstdint>

// ---------------------------------------------------------------------------
// GCN encoder: N=50000, E=500000, 128 -> 256 -> 512 -> 128
// Fused persistent CSR-prep (grid-barrier) + CSR gather aggregation
// + fp16 mma.sync tensor-core GEMM pipelines (R7 proven core)
// ---------------------------------------------------------------------------

#define MAXN 50048
#define MAXE 524288
#define EPS 1e-5f
#define PB 128          // prep blocks (<= SM count, all resident)
#define PT 1024         // prep threads per block

__device__ float  g_dinv[MAXN];
__device__ int    g_cnt[MAXN];
__device__ int    g_rowptr[MAXN + 1];
__device__ int    g_cursor[MAXN];
__device__ int    g_bsum[PB];
__device__ int2   g_adj[MAXE];                 // (src, bits(w))
__device__ __half g_agg1h[(size_t)MAXN * 128];
__device__ __half g_agg2h[(size_t)MAXN * 256];
__device__ __half g_h1[(size_t)MAXN * 256];    // fp16 raw (pre-BN)
__device__ __half g_h2[(size_t)MAXN * 512];
__device__ __half g_w1t[256 * 128];            // fp16 W1^T [N][K]
__device__ __half g_w2t[512 * 256];
__device__ __half g_wlt[128 * 512];
__device__ float2 g_stats1[256];
__device__ float2 g_stats2[512];
__device__ float2 g_ss1[256];
__device__ float2 g_ss2[512];
__device__ int    g_flag32;                    // sticky: set iff edges are int32
__device__ int    g_bar_cnt;                   // grid barrier state
__device__ volatile unsigned g_bar_gen;        // monotonic across replays

// ---------------------------------------------------------------------------

__device__ __forceinline__ void red_add_v2(float2* addr, float a, float b) {
    asm volatile("red.global.add.v2.f32 [%0], {%1,%2};"
                 :: "l"(addr), "f"(a), "f"(b) : "memory");
}

__device__ __forceinline__ int load_idx(const void* ei, long long pos, int is32) {
    if (is32) return ((const int*)ei)[pos];
    return (int)(((const long long*)ei)[pos]);
}

__device__ __forceinline__ uint32_t pack_h2(float lo, float hi) {
    uint32_t u;
    asm("cvt.rn.f16x2.f32 %0, %1, %2;" : "=r"(u) : "f"(hi), "f"(lo));
    return u;
}

__device__ __forceinline__ float2 unpack_h2(uint32_t u) {
    __half2 h = *(__half2*)&u;
    return __half22float2(h);
}

__device__ __forceinline__ void cp_async16(void* sptr, const void* gptr, int src_bytes) {
    uint32_t sa = (uint32_t)__cvta_generic_to_shared(sptr);
    asm volatile("cp.async.cg.shared.global [%0], [%1], 16, %2;"
                 :: "r"(sa), "l"(gptr), "r"(src_bytes));
}

// --- software grid barrier (all PB blocks guaranteed resident) ---------------
__device__ __forceinline__ void grid_bar() {
    __threadfence();
    __syncthreads();
    if (threadIdx.x == 0) {
        unsigned gen = g_bar_gen;
        if (atomicAdd(&g_bar_cnt, 1) == PB - 1) {
            g_bar_cnt = 0;
            __threadfence();
            g_bar_gen = gen + 1;
        } else {
            while (g_bar_gen == gen) { }
        }
    }
    __syncthreads();
    __threadfence();
}

// ---------------------------------------------------------------------------
// Fused CSR prep: zero+detect | count | scan | fill, one persistent kernel.
// ---------------------------------------------------------------------------
__global__ __launch_bounds__(PT, 1) void k_prep_fused(
        const void* __restrict__ ei, long long E, int n,
        int* __restrict__ cnt, int* __restrict__ rowptr, int* __restrict__ cursor,
        float* __restrict__ dinv, int* __restrict__ bsum, int2* __restrict__ adj,
        float2* st1, float2* st2, int d1, int d2, int* flag) {
    const int tid = blockIdx.x * PT + threadIdx.x;
    const int nth = PB * PT;
    const int lane = threadIdx.x & 31, wid = threadIdx.x >> 5;
    __shared__ int ws[32];
    __shared__ int s_off;

    // phase 0: zero cnt/stats, detect dtype (block 0 samples head)
    for (int i = tid; i < n; i += nth) cnt[i] = 0;
    if (tid < d1) st1[tid] = make_float2(0.f, 0.f);
    if (tid < d2) st2[tid] = make_float2(0.f, 0.f);
    if (blockIdx.x == 0) {
        long long lim = E < 8192 ? E : 8192;
        int any = 0;
        for (long long j = threadIdx.x; j < lim; j += PT)
            if (((const int*)ei)[2 * j + 1] != 0) any = 1;
        if (any) atomicOr(flag, 1);
    }
    grid_bar();

    const int is32 = *flag;

    // phase 1: in-degree counts
    for (long long i = tid; i < E; i += nth) {
        int d = load_idx(ei, E + i, is32);
        atomicAdd(&cnt[d], 1);
    }
    grid_bar();

    // phase 2a: block-local inclusive scan over chunk of C elements
    const int C = (n + PB - 1) / PB;           // <= PT
    const int idx = blockIdx.x * C + threadIdx.x;
    const int inC = (threadIdx.x < C && idx < n);
    int v = inC ? cnt[idx] : 0;
    int x = v;
#pragma unroll
    for (int off = 1; off < 32; off <<= 1) {
        int y = __shfl_up_sync(0xffffffffu, x, off);
        if (lane >= off) x += y;
    }
    if (lane == 31) ws[wid] = x;
    __syncthreads();
    if (wid == 0) {
        int w = ws[lane];
#pragma unroll
        for (int off = 1; off < 32; off <<= 1) {
            int y = __shfl_up_sync(0xffffffffu, w, off);
            if (lane >= off) w += y;
        }
        ws[lane] = w;
    }
    __syncthreads();
    int incl = x + (wid > 0 ? ws[wid - 1] : 0);
    int excl = incl - v;
    if (threadIdx.x == PT - 1) bsum[blockIdx.x] = incl;   // block total
    grid_bar();

    // phase 2b: block offset = sum(bsum[0..blockIdx.x)) and apply
    {
        int bv = ((int)threadIdx.x < blockIdx.x) ? bsum[threadIdx.x] : 0;
#pragma unroll
        for (int off = 16; off; off >>= 1) bv += __shfl_xor_sync(0xffffffffu, bv, off);
        if (lane == 0) ws[wid] = bv;
        __syncthreads();
        if (wid == 0) {
            int w = ws[lane];
#pragma unroll
            for (int off = 16; off; off >>= 1) w += __shfl_xor_sync(0xffffffffu, w, off);
            if (lane == 0) s_off = w;
        }
        __syncthreads();
    }
    if (inC) {
        int e0 = excl + s_off;
        rowptr[idx] = e0;
        cursor[idx] = e0;
        dinv[idx] = rsqrtf((float)v + 1.0f);
        if (idx == n - 1) rowptr[n] = (int)E;
    }
    grid_bar();

    // phase 3: bucket-fill adjacency
    for (long long i = tid; i < E; i += nth) {
        int s = load_idx(ei, i, is32);
        int d = load_idx(ei, E + i, is32);
        float w = dinv[s] * dinv[d];
        int pos = atomicAdd(&cursor[d], 1);
        adj[pos] = make_int2(s, __float_as_int(w));
    }
}

// --- weight convert: all three -> fp16 transposed [N][K] --------------------------
__global__ void k_cvtw(const float* __restrict__ W1, const float* __restrict__ W2,
                       const float* __restrict__ W3,
                       __half* __restrict__ t1, __half* __restrict__ t2,
                       __half* __restrict__ t3,
                       int K1, int N1, int K2, int N2, int K3, int N3) {
    int i = blockIdx.x * blockDim.x + threadIdx.x;
    if (i < K1 * N1) {
        int k = i / N1, n = i % N1;
        t1[n * K1 + k] = __float2half_rn(W1[i]);
    }
    if (i < K2 * N2) {
        int k = i / N2, n = i % N2;
        t2[n * K2 + k] = __float2half_rn(W2[i]);
    }
    if (i < K3 * N3) {
        int k = i / N3, n = i % N3;
        t3[n * K3 + k] = __float2half_rn(W3[i]);
    }
}

// --- agg layer 1: fp32 x in, fp16 out (R7 version) --------------------------------
__global__ __launch_bounds__(256) void k_agg1(const int2* __restrict__ adj,
                                              const int* __restrict__ rowptr,
                                              const float* __restrict__ dinv,
                                              const float* __restrict__ X,
                                              __half* __restrict__ out, int N) {
    int node = (blockIdx.x * blockDim.x + threadIdx.x) >> 5;
    int lane = threadIdx.x & 31;
    if (node >= N) return;
    float w0 = dinv[node]; w0 *= w0;
    float4 a = ((const float4*)(X + (size_t)node * 128))[lane];
    float4 acc = make_float4(a.x * w0, a.y * w0, a.z * w0, a.w * w0);
    int j = rowptr[node], end = rowptr[node + 1];
    int2 e = (j < end) ? adj[j] : make_int2(0, 0);
    for (; j < end; j++) {
        int2 cur = e;
        if (j + 1 < end) e = adj[j + 1];
        float w = __int_as_float(cur.y);
        float4 s = ((const float4*)(X + (size_t)cur.x * 128))[lane];
        acc.x += w * s.x; acc.y += w * s.y;
        acc.z += w * s.z; acc.w += w * s.w;
    }
    ((uint2*)(out + (size_t)node * 128))[lane] =
        make_uint2(pack_h2(acc.x, acc.y), pack_h2(acc.z, acc.w));
}

// --- agg layer 2: fp16 h1 in (BN+ReLU fused), fp16 out (R7 version) ---------------
__global__ __launch_bounds__(256) void k_agg2(const int2* __restrict__ adj,
                                              const int* __restrict__ rowptr,
                                              const float* __restrict__ dinv,
                                              const __half* __restrict__ X,
                                              __half* __restrict__ out, int N,
                                              const float2* __restrict__ ss) {
    int node = (blockIdx.x * blockDim.x + threadIdx.x) >> 5;
    int lane = threadIdx.x & 31;
    if (node >= N) return;
    float2 sr[8];
#pragma unroll
    for (int j = 0; j < 8; j++) sr[j] = ss[lane * 8 + j];

    float acc[8];
    float w0 = dinv[node]; w0 *= w0;
    {
        uint4 u = ((const uint4*)(X + (size_t)node * 256))[lane];
        float2 f0 = unpack_h2(u.x), f1 = unpack_h2(u.y);
        float2 f2 = unpack_h2(u.z), f3 = unpack_h2(u.w);
        float f[8] = {f0.x, f0.y, f1.x, f1.y, f2.x, f2.y, f3.x, f3.y};
#pragma unroll
        for (int j = 0; j < 8; j++)
            acc[j] = w0 * fmaxf(fmaf(f[j], sr[j].x, sr[j].y), 0.f);
    }
    int j = rowptr[node], end = rowptr[node + 1];
    int2 e = (j < end) ? adj[j] : make_int2(0, 0);
    for (; j < end; j++) {
        int2 cur = e;
        if (j + 1 < end) e = adj[j + 1];
        float w = __int_as_float(cur.y);
        uint4 u = ((const uint4*)(X + (size_t)cur.x * 256))[lane];
        float2 f0 = unpack_h2(u.x), f1 = unpack_h2(u.y);
        float2 f2 = unpack_h2(u.z), f3 = unpack_h2(u.w);
        float f[8] = {f0.x, f0.y, f1.x, f1.y, f2.x, f2.y, f3.x, f3.y};
#pragma unroll
        for (int jj = 0; jj < 8; jj++)
            acc[jj] += w * fmaxf(fmaf(f[jj], sr[jj].x, sr[jj].y), 0.f);
    }
    uint4 o;
    o.x = pack_h2(acc[0], acc[1]);
    o.y = pack_h2(acc[2], acc[3]);
    o.z = pack_h2(acc[4], acc[5]);
    o.w = pack_h2(acc[6], acc[7]);
    ((uint4*)(out + (size_t)node * 256))[lane] = o;
}

// ---------------------------------------------------------------------------
// fp16 mma.sync pipelined GEMM (R7 core): fused bias + fp32 BN stats, fp16 C.
// ---------------------------------------------------------------------------
#define GBM 128
#define GBN 128
#define HASTR 40
#define HTSZ (128 * HASTR)
#define SMEM_H ((4 * HTSZ) * 2)
#define SMEM_FINH (SMEM_H + 512 * 8)

__global__ __launch_bounds__(256) void k_gemm_h(const __half* __restrict__ A,
                                                const __half* __restrict__ Bt,
                                                const float* __restrict__ bias,
                                                __half* __restrict__ C,
                                                float2* __restrict__ stats,
                                                int M, int N, int K) {
    extern __shared__ __half smh[];
    __half* As = smh;
    __half* Bs = smh + 2 * HTSZ;

    const int tid  = threadIdx.x;
    const int lane = tid & 31;
    const int warpId = tid >> 5;
    const int warpM = warpId & 3;
    const int warpN = warpId >> 2;
    const int g = lane >> 2;
    const int t = lane & 3;
    const int bm = blockIdx.y * GBM;
    const int bn = blockIdx.x * GBN;

    const int l_row = tid >> 2;
    const int l_chk = (tid & 3) * 8;

    float4 acc[2][8];
#pragma unroll
    for (int i = 0; i < 2; i++)
#pragma unroll
        for (int j = 0; j < 8; j++)
            acc[i][j] = make_float4(0.f, 0.f, 0.f, 0.f);

    auto load_stage = [&](int stg, int k0) {
        __half* pa = As + stg * HTSZ;
        __half* pb = Bs + stg * HTSZ;
#pragma unroll
        for (int i = 0; i < 2; i++) {
            int row = i * 64 + l_row;
            int gm = bm + row;
            int ok = (gm < M) ? 16 : 0;
            int gmc = min(gm, M - 1);
            cp_async16(pa + row * HASTR + l_chk, A + (size_t)gmc * K + k0 + l_chk, ok);
        }
#pragma unroll
        for (int i = 0; i < 2; i++) {
            int row = i * 64 + l_row;
            cp_async16(pb + row * HASTR + l_chk, Bt + (size_t)(bn + row) * K + k0 + l_chk, 16);
        }
    };

    const int nk = K / 32;
    load_stage(0, 0);
    asm volatile("cp.async.commit_group;");

    for (int tk = 0; tk < nk; tk++) {
        if (tk + 1 < nk) {
            load_stage((tk + 1) & 1, (tk + 1) * 32);
            asm volatile("cp.async.commit_group;");
            asm volatile("cp.async.wait_group 1;");
        } else {
            asm volatile("cp.async.wait_group 0;");
        }
        __syncthreads();

        const __half* pa = As + (tk & 1) * HTSZ;
        const __half* pb = Bs + (tk & 1) * HTSZ;
#pragma unroll
        for (int kk = 0; kk < 32; kk += 16) {
            uint32_t afrag[2][4];
            uint32_t bfrag[8][2];
#pragma unroll
            for (int im = 0; im < 2; im++) {
                const __half* base = pa + (warpM * 32 + im * 16 + g) * HASTR + kk + 2 * t;
                afrag[im][0] = *(const uint32_t*)(base);
                afrag[im][1] = *(const uint32_t*)(base + 8 * HASTR);
                afrag[im][2] = *(const uint32_t*)(base + 8);
                afrag[im][3] = *(const uint32_t*)(base + 8 * HASTR + 8);
            }
#pragma unroll
            for (int jn = 0; jn < 8; jn++) {
                const __half* base = pb + (warpN * 64 + jn * 8 + g) * HASTR + kk + 2 * t;
                bfrag[jn][0] = *(const uint32_t*)(base);
                bfrag[jn][1] = *(const uint32_t*)(base + 8);
            }
#pragma unroll
            for (int im = 0; im < 2; im++)
#pragma unroll
                for (int jn = 0; jn < 8; jn++) {
                    float4& c = acc[im][jn];
                    asm volatile(
                        "mma.sync.aligned.m16n8k16.row.col.f32.f16.f16.f32 "
                        "{%0,%1,%2,%3}, {%4,%5,%6,%7}, {%8,%9}, {%0,%1,%2,%3};"
                        : "+f"(c.x), "+f"(c.y), "+f"(c.z), "+f"(c.w)
                        : "r"(afrag[im][0]), "r"(afrag[im][1]),
                          "r"(afrag[im][2]), "r"(afrag[im][3]),
                          "r"(bfrag[jn][0]), "r"(bfrag[jn][1]));
                }
        }
        __syncthreads();
    }

#pragma unroll
    for (int jn = 0; jn < 8; jn++) {
        int col = bn + warpN * 64 + jn * 8 + 2 * t;
        float bx = bias[col], by = bias[col + 1];
        float s0 = 0.f, q0 = 0.f, s1 = 0.f, q1 = 0.f;
#pragma unroll
        for (int im = 0; im < 2; im++) {
            int row0 = bm + warpM * 32 + im * 16 + g;
            float4 c = acc[im][jn];
            if (row0 < M) {
                float ox = c.x + bx, oy = c.y + by;
                *(uint32_t*)(C + (size_t)row0 * N + col) = pack_h2(ox, oy);
                s0 += ox; q0 += ox * ox; s1 += oy; q1 += oy * oy;
            }
            if (row0 + 8 < M) {
                float oz = c.z + bx, ow = c.w + by;
                *(uint32_t*)(C + (size_t)(row0 + 8) * N + col) = pack_h2(oz, ow);
                s0 += oz; q0 += oz * oz; s1 += ow; q1 += ow * ow;
            }
        }
#pragma unroll
        for (int m = 4; m < 32; m <<= 1) {
            s0 += __shfl_xor_sync(0xffffffffu, s0, m);
            q0 += __shfl_xor_sync(0xffffffffu, q0, m);
            s1 += __shfl_xor_sync(0xffffffffu, s1, m);
            q1 += __shfl_xor_sync(0xffffffffu, q1, m);
        }
        if (g == 0) {
            red_add_v2(&stats[col], s0, q0);
            red_add_v2(&stats[col + 1], s1, q1);
        }
    }
}

// ---------------------------------------------------------------------------
// Final fp16 GEMM (R7 core): BN2+ReLU applied to A frags at build, fp32 out.
// ---------------------------------------------------------------------------
__global__ __launch_bounds__(256) void k_gemm_finh(const __half* __restrict__ A,
                                                   const __half* __restrict__ Bt,
                                                   const float* __restrict__ bias,
                                                   float* __restrict__ C,
                                                   const float2* __restrict__ ssA,
                                                   int M, int N, int K) {
    extern __shared__ __half smh[];
    __half* As = smh;
    __half* Bs = smh + 2 * HTSZ;
    float2* ssm = (float2*)(smh + 4 * HTSZ);

    const int tid  = threadIdx.x;
    const int lane = tid & 31;
    const int warpId = tid >> 5;
    const int warpM = warpId & 3;
    const int warpN = warpId >> 2;
    const int g = lane >> 2;
    const int t = lane & 3;
    const int bm = blockIdx.y * GBM;
    const int bn = blockIdx.x * GBN;

    for (int c = tid; c < K; c += 256) ssm[c] = ssA[c];

    const int l_row = tid >> 2;
    const int l_chk = (tid & 3) * 8;

    float4 acc[2][8];
#pragma unroll
    for (int i = 0; i < 2; i++)
#pragma unroll
        for (int j = 0; j < 8; j++)
            acc[i][j] = make_float4(0.f, 0.f, 0.f, 0.f);

    auto load_stage = [&](int stg, int k0) {
        __half* pa = As + stg * HTSZ;
        __half* pb = Bs + stg * HTSZ;
#pragma unroll
        for (int i = 0; i < 2; i++) {
            int row = i * 64 + l_row;
            int gm = bm + row;
            int ok = (gm < M) ? 16 : 0;
            int gmc = min(gm, M - 1);
            cp_async16(pa + row * HASTR + l_chk, A + (size_t)gmc * K + k0 + l_chk, ok);
        }
#pragma unroll
        for (int i = 0; i < 2; i++) {
            int row = i * 64 + l_row;
            cp_async16(pb + row * HASTR + l_chk, Bt + (size_t)(bn + row) * K + k0 + l_chk, 16);
        }
    };

    const int nk = K / 32;
    load_stage(0, 0);
    asm volatile("cp.async.commit_group;");

    for (int tk = 0; tk < nk; tk++) {
        if (tk + 1 < nk) {
            load_stage((tk + 1) & 1, (tk + 1) * 32);
            asm volatile("cp.async.commit_group;");
            asm volatile("cp.async.wait_group 1;");
        } else {
            asm volatile("cp.async.wait_group 0;");
        }
        __syncthreads();

        const __half* pa = As + (tk & 1) * HTSZ;
        const __half* pb = Bs + (tk & 1) * HTSZ;
        const int kbase = tk * 32;
#pragma unroll
        for (int kk = 0; kk < 32; kk += 16) {
            int kc = kbase + kk + 2 * t;
            float2 s0 = ssm[kc],     s1 = ssm[kc + 1];
            float2 s2 = ssm[kc + 8], s3 = ssm[kc + 9];
            uint32_t afrag[2][4];
            uint32_t bfrag[8][2];
#pragma unroll
            for (int im = 0; im < 2; im++) {
                const __half* base = pa + (warpM * 32 + im * 16 + g) * HASTR + kk + 2 * t;
                float2 f0 = unpack_h2(*(const uint32_t*)(base));
                float2 f1 = unpack_h2(*(const uint32_t*)(base + 8 * HASTR));
                float2 f2 = unpack_h2(*(const uint32_t*)(base + 8));
                float2 f3 = unpack_h2(*(const uint32_t*)(base + 8 * HASTR + 8));
                afrag[im][0] = pack_h2(fmaxf(fmaf(f0.x, s0.x, s0.y), 0.f),
                                       fmaxf(fmaf(f0.y, s1.x, s1.y), 0.f));
                afrag[im][1] = pack_h2(fmaxf(fmaf(f1.x, s0.x, s0.y), 0.f),
                                       fmaxf(fmaf(f1.y, s1.x, s1.y), 0.f));
                afrag[im][2] = pack_h2(fmaxf(fmaf(f2.x, s2.x, s2.y), 0.f),
                                       fmaxf(fmaf(f2.y, s3.x, s3.y), 0.f));
                afrag[im][3] = pack_h2(fmaxf(fmaf(f3.x, s2.x, s2.y), 0.f),
                                       fmaxf(fmaf(f3.y, s3.x, s3.y), 0.f));
            }
#pragma unroll
            for (int jn = 0; jn < 8; jn++) {
                const __half* base = pb + (warpN * 64 + jn * 8 + g) * HASTR + kk + 2 * t;
                bfrag[jn][0] = *(const uint32_t*)(base);
                bfrag[jn][1] = *(const uint32_t*)(base + 8);
            }
#pragma unroll
            for (int im = 0; im < 2; im++)
#pragma unroll
                for (int jn = 0; jn < 8; jn++) {
                    float4& c = acc[im][jn];
                    asm volatile(
                        "mma.sync.aligned.m16n8k16.row.col.f32.f16.f16.f32 "
                        "{%0,%1,%2,%3}, {%4,%5,%6,%7}, {%8,%9}, {%0,%1,%2,%3};"
                        : "+f"(c.x), "+f"(c.y), "+f"(c.z), "+f"(c.w)
                        : "r"(afrag[im][0]), "r"(afrag[im][1]),
                          "r"(afrag[im][2]), "r"(afrag[im][3]),
                          "r"(bfrag[jn][0]), "r"(bfrag[jn][1]));
                }
        }
        __syncthreads();
    }

#pragma unroll
    for (int jn = 0; jn < 8; jn++) {
        int col = bn + warpN * 64 + jn * 8 + 2 * t;
        float bx = bias[col], by = bias[col + 1];
#pragma unroll
        for (int im = 0; im < 2; im++) {
            int row0 = bm + warpM * 32 + im * 16 + g;
            float4 c = acc[im][jn];
            if (row0 < M)
                *(float2*)(C + (size_t)row0 * N + col) = make_float2(c.x + bx, c.y + by);
            if (row0 + 8 < M)
                *(float2*)(C + (size_t)(row0 + 8) * N + col) = make_float2(c.z + bx, c.w + by);
        }
    }
}

// --- stats -> per-col (scale, shift) ------------------------------------------
__global__ void k_bnprep(const float2* __restrict__ stats,
                         const float* __restrict__ gamma,
                         const float* __restrict__ beta,
                         float2* __restrict__ ss, int D, float invM) {
    int c = blockIdx.x * blockDim.x + threadIdx.x;
    if (c < D) {
        float mu = stats[c].x * invM;
        float var = stats[c].y * invM - mu * mu;
        float sc = gamma[c] * rsqrtf(var + EPS);
        ss[c] = make_float2(sc, beta[c] - mu * sc);
    }
}

// ---------------------------------------------------------------------------

extern "C" void kernel_launch(void* const* d_in, const int* in_sizes, int n_in,
                              void* d_out, int out_size) {
    const float* x      = (const float*)d_in[0];
    const void*  ei     = d_in[1];
    const float* W1     = (const float*)d_in[2];
    const float* b1     = (const float*)d_in[3];
    const float* gamma1 = (const float*)d_in[4];
    const float* beta1  = (const float*)d_in[5];
    const float* W2     = (const float*)d_in[6];
    const float* b2     = (const float*)d_in[7];
    const float* gamma2 = (const float*)d_in[8];
    const float* beta2  = (const float*)d_in[9];
    const float* Wl     = (const float*)d_in[10];
    const float* bl     = (const float*)d_in[11];

    const int H1   = in_sizes[3];               // 256
    const int H2   = in_sizes[7];               // 512
    const int DOUT = in_sizes[11];              // 128
    const int DIN  = in_sizes[2] / H1;          // 128
    const int N    = in_sizes[0] / DIN;         // 50000
    const long long E = in_sizes[1] / 2;        // 500000
    const float invM = 1.0f / (float)N;

    float *dinv;
    __half *agg1h, *agg2h, *h1, *h2, *w1t, *w2t, *wlt;
    float2 *stats1, *stats2, *ss1, *ss2;
    int *cnt, *rowptr, *cursor, *flag, *bsum;
    int2* adj;
    cudaGetSymbolAddress((void**)&dinv,   g_dinv);
    cudaGetSymbolAddress((void**)&cnt,    g_cnt);
    cudaGetSymbolAddress((void**)&rowptr, g_rowptr);
    cudaGetSymbolAddress((void**)&cursor, g_cursor);
    cudaGetSymbolAddress((void**)&bsum,   g_bsum);
    cudaGetSymbolAddress((void**)&adj,    g_adj);
    cudaGetSymbolAddress((void**)&agg1h,  g_agg1h);
    cudaGetSymbolAddress((void**)&agg2h,  g_agg2h);
    cudaGetSymbolAddress((void**)&h1,     g_h1);
    cudaGetSymbolAddress((void**)&h2,     g_h2);
    cudaGetSymbolAddress((void**)&w1t,    g_w1t);
    cudaGetSymbolAddress((void**)&w2t,    g_w2t);
    cudaGetSymbolAddress((void**)&wlt,    g_wlt);
    cudaGetSymbolAddress((void**)&stats1, g_stats1);
    cudaGetSymbolAddress((void**)&stats2, g_stats2);
    cudaGetSymbolAddress((void**)&ss1,    g_ss1);
    cudaGetSymbolAddress((void**)&ss2,    g_ss2);
    cudaGetSymbolAddress((void**)&flag,   g_flag32);

    float* out = (float*)d_out;

    cudaFuncSetAttribute(k_gemm_h,    cudaFuncAttributeMaxDynamicSharedMemorySize, SMEM_H);
    cudaFuncSetAttribute(k_gemm_finh, cudaFuncAttributeMaxDynamicSharedMemorySize, SMEM_FINH);

    const int aggBlocks = (int)(((long long)N * 32 + 255) / 256);

    // 1: independent weight conversion
    k_cvtw<<<(H1 * H2 + 255) / 256, 256>>>(W1, W2, Wl, w1t, w2t, wlt,
                                           DIN, H1, H1, H2, H2, DOUT);
    // 2: fused CSR prep (zero/detect -> count -> scan -> fill)
    k_prep_fused<<<PB, PT>>>(ei, E, N, cnt, rowptr, cursor, dinv, bsum, adj,
                             stats1, stats2, H1, H2, flag);
    // 3: layer-1 aggregation (profiled slot)
    k_agg1<<<aggBlocks, 256>>>(adj, rowptr, dinv, x, agg1h, N);
    // 4: layer-1 GEMM (profiled slot)
    {
        dim3 grid(H1 / GBN, (N + GBM - 1) / GBM);
        k_gemm_h<<<grid, 256, SMEM_H>>>(agg1h, w1t, b1, h1, stats1, N, H1, DIN);
        k_bnprep<<<(H1 + 255) / 256, 256>>>(stats1, gamma1, beta1, ss1, H1, invM);
    }
    // layer 2
    k_agg2<<<aggBlocks, 256>>>(adj, rowptr, dinv, h1, agg2h, N, ss1);
    {
        dim3 grid(H2 / GBN, (N + GBM - 1) / GBM);
        k_gemm_h<<<grid, 256, SMEM_H>>>(agg2h, w2t, b2, h2, stats2, N, H2, H1);
        k_bnprep<<<(H2 + 255) / 256, 256>>>(stats2, gamma2, beta2, ss2, H2, invM);
    }
    // final projection
    {
        dim3 grid(DOUT / GBN, (N + GBM - 1) / GBM);
        k_gemm_finh<<<grid, 256, SMEM_FINH>>>(h2, wlt, bl, out, ss2, N, DOUT, H2);
    }
}

// round 12
// speedup vs baseline: 1.0196x; 1.0073x over previous
#include <cuda_runtime.h>
#include <cuda_bf16.h>
#include <cuda_fp16.h>
#include <cstdint>

// ---------------------------------------------------------------------------
// GCN encoder: N=50000, E=500000, 128 -> 256 -> 512 -> 128
// CSR gather aggregation + fp16 mma.sync GEMMs, 64x128 CTA tiles (occupancy)
// ---------------------------------------------------------------------------

#define MAXN 50048
#define MAXE 524288
#define EPS 1e-5f
#define SCAN_BLK 1024

__device__ float  g_dinv[MAXN];
__device__ int    g_cnt[MAXN];
__device__ int    g_rowptr[MAXN + 1];
__device__ int    g_cursor[MAXN];
__device__ int    g_bsum[64];
__device__ int2   g_adj[MAXE];                 // (src, bits(w))
__device__ __half g_agg1h[(size_t)MAXN * 128];
__device__ __half g_agg2h[(size_t)MAXN * 256];
__device__ __half g_h1[(size_t)MAXN * 256];    // fp16 raw (pre-BN)
__device__ __half g_h2[(size_t)MAXN * 512];
__device__ __half g_w1t[256 * 128];            // fp16 W1^T [N][K]
__device__ __half g_w2t[512 * 256];
__device__ __half g_wlt[128 * 512];
__device__ float2 g_stats1[256];
__device__ float2 g_stats2[512];
__device__ float2 g_ss1[256];
__device__ float2 g_ss2[512];
__device__ int    g_flag32;

// ---------------------------------------------------------------------------

__device__ __forceinline__ void red_add_v2(float2* addr, float a, float b) {
    asm volatile("red.global.add.v2.f32 [%0], {%1,%2};"
                 :: "l"(addr), "f"(a), "f"(b) : "memory");
}

__device__ __forceinline__ int load_idx(const void* ei, long long pos, int is32) {
    if (is32) return ((const int*)ei)[pos];
    return (int)(((const long long*)ei)[pos]);
}

__device__ __forceinline__ uint32_t pack_h2(float lo, float hi) {
    uint32_t u;
    asm("cvt.rn.f16x2.f32 %0, %1, %2;" : "=r"(u) : "f"(hi), "f"(lo));
    return u;
}

__device__ __forceinline__ float2 unpack_h2(uint32_t u) {
    __half2 h = *(__half2*)&u;
    return __half22float2(h);
}

__device__ __forceinline__ void cp_async16(void* sptr, const void* gptr, int src_bytes) {
    uint32_t sa = (uint32_t)__cvta_generic_to_shared(sptr);
    asm volatile("cp.async.cg.shared.global [%0], [%1], 16, %2;"
                 :: "r"(sa), "l"(gptr), "r"(src_bytes));
}

// --- prep0 (+fused dtype detect on block 0): zero cnt + stats ----------------
__global__ void k_prep0(const int* __restrict__ ei32, long long E,
                        int* cnt, int n, float2* st1, float2* st2,
                        int d1, int d2, int* flag) {
    int i = blockIdx.x * blockDim.x + threadIdx.x;
    if (blockIdx.x == 0) {
        long long lim = E < 8192 ? E : 8192;
        int any = 0;
        for (long long j = threadIdx.x; j < lim; j += blockDim.x)
            if (ei32[2 * j + 1] != 0) any = 1;
        if (any) atomicOr(flag, 1);
    }
    if (i < n) cnt[i] = 0;
    if (i < d1) st1[i] = make_float2(0.f, 0.f);
    if (i < d2) st2[i] = make_float2(0.f, 0.f);
}

// --- in-degree counts ---------------------------------------------------------
__global__ void k_count(const void* ei, long long E, const int* flag, int* cnt) {
    long long i = blockIdx.x * (long long)blockDim.x + threadIdx.x;
    long long stride = (long long)gridDim.x * blockDim.x;
    int is32 = *flag;
    for (; i < E; i += stride) {
        int d = load_idx(ei, E + i, is32);
        atomicAdd(&cnt[d], 1);
    }
}

// --- scan pass 1 ---------------------------------------------------------------
__global__ __launch_bounds__(SCAN_BLK) void k_scan_red(const int* __restrict__ cnt,
                                                       int* __restrict__ bsum, int n) {
    int i = blockIdx.x * SCAN_BLK + threadIdx.x;
    int v = (i < n) ? cnt[i] : 0;
    int lane = threadIdx.x & 31, wid = threadIdx.x >> 5;
#pragma unroll
    for (int off = 16; off; off >>= 1) v += __shfl_xor_sync(0xffffffffu, v, off);
    __shared__ int ws[32];
    if (lane == 0) ws[wid] = v;
    __syncthreads();
    if (wid == 0) {
        v = ws[lane];
#pragma unroll
        for (int off = 16; off; off >>= 1) v += __shfl_xor_sync(0xffffffffu, v, off);
        if (lane == 0) bsum[blockIdx.x] = v;
    }
}

// --- scan pass 2 ---------------------------------------------------------------
__global__ __launch_bounds__(SCAN_BLK) void k_scan_apply(const int* __restrict__ cnt,
                                                         const int* __restrict__ bsum, int nb,
                                                         int* __restrict__ rowptr,
                                                         int* __restrict__ cursor,
                                                         float* __restrict__ dinv, int n) {
    int tid = threadIdx.x;
    int lane = tid & 31, wid = tid >> 5;
    __shared__ int ws[32];
    __shared__ int s_off;

    int b = (tid < nb && tid < blockIdx.x) ? bsum[tid] : 0;
#pragma unroll
    for (int off = 16; off; off >>= 1) b += __shfl_xor_sync(0xffffffffu, b, off);
    if (lane == 0) ws[wid] = b;
    __syncthreads();
    if (wid == 0) {
        int w = ws[lane];
#pragma unroll
        for (int off = 16; off; off >>= 1) w += __shfl_xor_sync(0xffffffffu, w, off);
        if (lane == 0) s_off = w;
    }
    __syncthreads();
    int offset = s_off;
    __syncthreads();

    int i = blockIdx.x * SCAN_BLK + tid;
    int v = (i < n) ? cnt[i] : 0;
    int x = v;
#pragma unroll
    for (int off = 1; off < 32; off <<= 1) {
        int y = __shfl_up_sync(0xffffffffu, x, off);
        if (lane >= off) x += y;
    }
    if (lane == 31) ws[wid] = x;
    __syncthreads();
    if (wid == 0) {
        int w = ws[lane];
#pragma unroll
        for (int off = 1; off < 32; off <<= 1) {
            int y = __shfl_up_sync(0xffffffffu, w, off);
            if (lane >= off) w += y;
        }
        ws[lane] = w;
    }
    __syncthreads();
    int incl = x + (wid > 0 ? ws[wid - 1] : 0);
    int excl = incl - v + offset;
    if (i < n) {
        rowptr[i] = excl;
        cursor[i] = excl;
        dinv[i] = rsqrtf((float)v + 1.0f);
        if (i == n - 1) rowptr[n] = excl + v;
    }
}

// --- bucket-fill adjacency -------------------------------------------------------
__global__ void k_fill(const void* __restrict__ ei, long long E, const int* flag,
                       const float* __restrict__ dinv, int* __restrict__ cursor,
                       int2* __restrict__ adj) {
    long long i = blockIdx.x * (long long)blockDim.x + threadIdx.x;
    long long stride = (long long)gridDim.x * blockDim.x;
    int is32 = *flag;
    for (; i < E; i += stride) {
        int s = load_idx(ei, i, is32);
        int d = load_idx(ei, E + i, is32);
        float w = dinv[s] * dinv[d];
        int pos = atomicAdd(&cursor[d], 1);
        adj[pos] = make_int2(s, __float_as_int(w));
    }
}

// --- weight convert: all three -> fp16 transposed [N][K] --------------------------
__global__ void k_cvtw(const float* __restrict__ W1, const float* __restrict__ W2,
                       const float* __restrict__ W3,
                       __half* __restrict__ t1, __half* __restrict__ t2,
                       __half* __restrict__ t3,
                       int K1, int N1, int K2, int N2, int K3, int N3) {
    int i = blockIdx.x * blockDim.x + threadIdx.x;
    if (i < K1 * N1) {
        int k = i / N1, n = i % N1;
        t1[n * K1 + k] = __float2half_rn(W1[i]);
    }
    if (i < K2 * N2) {
        int k = i / N2, n = i % N2;
        t2[n * K2 + k] = __float2half_rn(W2[i]);
    }
    if (i < K3 * N3) {
        int k = i / N3, n = i % N3;
        t3[n * K3 + k] = __float2half_rn(W3[i]);
    }
}

// --- agg layer 1: fp32 x in, fp16 out (R7) ----------------------------------------
__global__ __launch_bounds__(256) void k_agg1(const int2* __restrict__ adj,
                                              const int* __restrict__ rowptr,
                                              const float* __restrict__ dinv,
                                              const float* __restrict__ X,
                                              __half* __restrict__ out, int N) {
    int node = (blockIdx.x * blockDim.x + threadIdx.x) >> 5;
    int lane = threadIdx.x & 31;
    if (node >= N) return;
    float w0 = dinv[node]; w0 *= w0;
    float4 a = ((const float4*)(X + (size_t)node * 128))[lane];
    float4 acc = make_float4(a.x * w0, a.y * w0, a.z * w0, a.w * w0);
    int j = rowptr[node], end = rowptr[node + 1];
    int2 e = (j < end) ? adj[j] : make_int2(0, 0);
    for (; j < end; j++) {
        int2 cur = e;
        if (j + 1 < end) e = adj[j + 1];
        float w = __int_as_float(cur.y);
        float4 s = ((const float4*)(X + (size_t)cur.x * 128))[lane];
        acc.x += w * s.x; acc.y += w * s.y;
        acc.z += w * s.z; acc.w += w * s.w;
    }
    ((uint2*)(out + (size_t)node * 128))[lane] =
        make_uint2(pack_h2(acc.x, acc.y), pack_h2(acc.z, acc.w));
}

// --- agg layer 2: fp16 h1 in (BN+ReLU fused), fp16 out (R7) -----------------------
__global__ __launch_bounds__(256) void k_agg2(const int2* __restrict__ adj,
                                              const int* __restrict__ rowptr,
                                              const float* __restrict__ dinv,
                                              const __half* __restrict__ X,
                                              __half* __restrict__ out, int N,
                                              const float2* __restrict__ ss) {
    int node = (blockIdx.x * blockDim.x + threadIdx.x) >> 5;
    int lane = threadIdx.x & 31;
    if (node >= N) return;
    float2 sr[8];
#pragma unroll
    for (int j = 0; j < 8; j++) sr[j] = ss[lane * 8 + j];

    float acc[8];
    float w0 = dinv[node]; w0 *= w0;
    {
        uint4 u = ((const uint4*)(X + (size_t)node * 256))[lane];
        float2 f0 = unpack_h2(u.x), f1 = unpack_h2(u.y);
        float2 f2 = unpack_h2(u.z), f3 = unpack_h2(u.w);
        float f[8] = {f0.x, f0.y, f1.x, f1.y, f2.x, f2.y, f3.x, f3.y};
#pragma unroll
        for (int j = 0; j < 8; j++)
            acc[j] = w0 * fmaxf(fmaf(f[j], sr[j].x, sr[j].y), 0.f);
    }
    int j = rowptr[node], end = rowptr[node + 1];
    int2 e = (j < end) ? adj[j] : make_int2(0, 0);
    for (; j < end; j++) {
        int2 cur = e;
        if (j + 1 < end) e = adj[j + 1];
        float w = __int_as_float(cur.y);
        uint4 u = ((const uint4*)(X + (size_t)cur.x * 256))[lane];
        float2 f0 = unpack_h2(u.x), f1 = unpack_h2(u.y);
        float2 f2 = unpack_h2(u.z), f3 = unpack_h2(u.w);
        float f[8] = {f0.x, f0.y, f1.x, f1.y, f2.x, f2.y, f3.x, f3.y};
#pragma unroll
        for (int jj = 0; jj < 8; jj++)
            acc[jj] += w * fmaxf(fmaf(f[jj], sr[jj].x, sr[jj].y), 0.f);
    }
    uint4 o;
    o.x = pack_h2(acc[0], acc[1]);
    o.y = pack_h2(acc[2], acc[3]);
    o.z = pack_h2(acc[4], acc[5]);
    o.w = pack_h2(acc[6], acc[7]);
    ((uint4*)(out + (size_t)node * 256))[lane] = o;
}

// ---------------------------------------------------------------------------
// fp16 mma.sync pipelined GEMM, CTA tile 64x128, 8 warps (warp 32x32).
// cp.async 2-stage, fused bias + fp32 BN stats, fp16 C.
// ---------------------------------------------------------------------------
#define GBM 64
#define GBN 128
#define HASTR 40
#define ASZ2 (64 * HASTR)          // halves per A stage
#define BSZ2 (128 * HASTR)         // halves per B stage
#define SMEM_H ((2 * ASZ2 + 2 * BSZ2) * 2)
#define SMEM_FINH (SMEM_H + 512 * 8)

__global__ __launch_bounds__(256) void k_gemm_h(const __half* __restrict__ A,
                                                const __half* __restrict__ Bt,
                                                const float* __restrict__ bias,
                                                __half* __restrict__ C,
                                                float2* __restrict__ stats,
                                                int M, int N, int K) {
    extern __shared__ __half smh[];
    __half* As = smh;                   // 2 stages of ASZ2
    __half* Bs = smh + 2 * ASZ2;        // 2 stages of BSZ2

    const int tid  = threadIdx.x;
    const int lane = tid & 31;
    const int warpId = tid >> 5;
    const int warpM = warpId & 1;       // 2 M-slices of 32
    const int warpN = warpId >> 1;      // 4 N-slices of 32
    const int g = lane >> 2;
    const int t = lane & 3;
    const int bm = blockIdx.y * GBM;
    const int bn = blockIdx.x * GBN;

    const int l_row = tid >> 2;         // 0..63
    const int l_chk = (tid & 3) * 8;    // half offset of 16B chunk

    float4 acc[2][4];
#pragma unroll
    for (int i = 0; i < 2; i++)
#pragma unroll
        for (int j = 0; j < 4; j++)
            acc[i][j] = make_float4(0.f, 0.f, 0.f, 0.f);

    auto load_stage = [&](int stg, int k0) {
        __half* pa = As + stg * ASZ2;
        __half* pb = Bs + stg * BSZ2;
        {
            int row = l_row;
            int gm = bm + row;
            int ok = (gm < M) ? 16 : 0;
            int gmc = min(gm, M - 1);
            cp_async16(pa + row * HASTR + l_chk, A + (size_t)gmc * K + k0 + l_chk, ok);
        }
#pragma unroll
        for (int i = 0; i < 2; i++) {
            int row = i * 64 + l_row;
            cp_async16(pb + row * HASTR + l_chk, Bt + (size_t)(bn + row) * K + k0 + l_chk, 16);
        }
    };

    const int nk = K / 32;
    load_stage(0, 0);
    asm volatile("cp.async.commit_group;");

    for (int tk = 0; tk < nk; tk++) {
        if (tk + 1 < nk) {
            load_stage((tk + 1) & 1, (tk + 1) * 32);
            asm volatile("cp.async.commit_group;");
            asm volatile("cp.async.wait_group 1;");
        } else {
            asm volatile("cp.async.wait_group 0;");
        }
        __syncthreads();

        const __half* pa = As + (tk & 1) * ASZ2;
        const __half* pb = Bs + (tk & 1) * BSZ2;
#pragma unroll
        for (int kk = 0; kk < 32; kk += 16) {
            uint32_t afrag[2][4];
            uint32_t bfrag[4][2];
#pragma unroll
            for (int im = 0; im < 2; im++) {
                const __half* base = pa + (warpM * 32 + im * 16 + g) * HASTR + kk + 2 * t;
                afrag[im][0] = *(const uint32_t*)(base);
                afrag[im][1] = *(const uint32_t*)(base + 8 * HASTR);
                afrag[im][2] = *(const uint32_t*)(base + 8);
                afrag[im][3] = *(const uint32_t*)(base + 8 * HASTR + 8);
            }
#pragma unroll
            for (int jn = 0; jn < 4; jn++) {
                const __half* base = pb + (warpN * 32 + jn * 8 + g) * HASTR + kk + 2 * t;
                bfrag[jn][0] = *(const uint32_t*)(base);
                bfrag[jn][1] = *(const uint32_t*)(base + 8);
            }
#pragma unroll
            for (int im = 0; im < 2; im++)
#pragma unroll
                for (int jn = 0; jn < 4; jn++) {
                    float4& c = acc[im][jn];
                    asm volatile(
                        "mma.sync.aligned.m16n8k16.row.col.f32.f16.f16.f32 "
                        "{%0,%1,%2,%3}, {%4,%5,%6,%7}, {%8,%9}, {%0,%1,%2,%3};"
                        : "+f"(c.x), "+f"(c.y), "+f"(c.z), "+f"(c.w)
                        : "r"(afrag[im][0]), "r"(afrag[im][1]),
                          "r"(afrag[im][2]), "r"(afrag[im][3]),
                          "r"(bfrag[jn][0]), "r"(bfrag[jn][1]));
                }
        }
        __syncthreads();
    }

#pragma unroll
    for (int jn = 0; jn < 4; jn++) {
        int col = bn + warpN * 32 + jn * 8 + 2 * t;
        float bx = bias[col], by = bias[col + 1];
        float s0 = 0.f, q0 = 0.f, s1 = 0.f, q1 = 0.f;
#pragma unroll
        for (int im = 0; im < 2; im++) {
            int row0 = bm + warpM * 32 + im * 16 + g;
            float4 c = acc[im][jn];
            if (row0 < M) {
                float ox = c.x + bx, oy = c.y + by;
                *(uint32_t*)(C + (size_t)row0 * N + col) = pack_h2(ox, oy);
                s0 += ox; q0 += ox * ox; s1 += oy; q1 += oy * oy;
            }
            if (row0 + 8 < M) {
                float oz = c.z + bx, ow = c.w + by;
                *(uint32_t*)(C + (size_t)(row0 + 8) * N + col) = pack_h2(oz, ow);
                s0 += oz; q0 += oz * oz; s1 += ow; q1 += ow * ow;
            }
        }
#pragma unroll
        for (int m = 4; m < 32; m <<= 1) {
            s0 += __shfl_xor_sync(0xffffffffu, s0, m);
            q0 += __shfl_xor_sync(0xffffffffu, q0, m);
            s1 += __shfl_xor_sync(0xffffffffu, s1, m);
            q1 += __shfl_xor_sync(0xffffffffu, q1, m);
        }
        if (g == 0) {
            red_add_v2(&stats[col], s0, q0);
            red_add_v2(&stats[col + 1], s1, q1);
        }
    }
}

// ---------------------------------------------------------------------------
// Final fp16 GEMM, 64x128 tile: BN2+ReLU applied to A frags at build, fp32 out.
// ---------------------------------------------------------------------------
__global__ __launch_bounds__(256) void k_gemm_finh(const __half* __restrict__ A,
                                                   const __half* __restrict__ Bt,
                                                   const float* __restrict__ bias,
                                                   float* __restrict__ C,
                                                   const float2* __restrict__ ssA,
                                                   int M, int N, int K) {
    extern __shared__ __half smh[];
    __half* As = smh;
    __half* Bs = smh + 2 * ASZ2;
    float2* ssm = (float2*)(smh + 2 * ASZ2 + 2 * BSZ2);

    const int tid  = threadIdx.x;
    const int lane = tid & 31;
    const int warpId = tid >> 5;
    const int warpM = warpId & 1;
    const int warpN = warpId >> 1;
    const int g = lane >> 2;
    const int t = lane & 3;
    const int bm = blockIdx.y * GBM;
    const int bn = blockIdx.x * GBN;

    for (int c = tid; c < K; c += 256) ssm[c] = ssA[c];

    const int l_row = tid >> 2;
    const int l_chk = (tid & 3) * 8;

    float4 acc[2][4];
#pragma unroll
    for (int i = 0; i < 2; i++)
#pragma unroll
        for (int j = 0; j < 4; j++)
            acc[i][j] = make_float4(0.f, 0.f, 0.f, 0.f);

    auto load_stage = [&](int stg, int k0) {
        __half* pa = As + stg * ASZ2;
        __half* pb = Bs + stg * BSZ2;
        {
            int row = l_row;
            int gm = bm + row;
            int ok = (gm < M) ? 16 : 0;
            int gmc = min(gm, M - 1);
            cp_async16(pa + row * HASTR + l_chk, A + (size_t)gmc * K + k0 + l_chk, ok);
        }
#pragma unroll
        for (int i = 0; i < 2; i++) {
            int row = i * 64 + l_row;
            cp_async16(pb + row * HASTR + l_chk, Bt + (size_t)(bn + row) * K + k0 + l_chk, 16);
        }
    };

    const int nk = K / 32;
    load_stage(0, 0);
    asm volatile("cp.async.commit_group;");

    for (int tk = 0; tk < nk; tk++) {
        if (tk + 1 < nk) {
            load_stage((tk + 1) & 1, (tk + 1) * 32);
            asm volatile("cp.async.commit_group;");
            asm volatile("cp.async.wait_group 1;");
        } else {
            asm volatile("cp.async.wait_group 0;");
        }
        __syncthreads();

        const __half* pa = As + (tk & 1) * ASZ2;
        const __half* pb = Bs + (tk & 1) * BSZ2;
        const int kbase = tk * 32;
#pragma unroll
        for (int kk = 0; kk < 32; kk += 16) {
            int kc = kbase + kk + 2 * t;
            float2 s0 = ssm[kc],     s1 = ssm[kc + 1];
            float2 s2 = ssm[kc + 8], s3 = ssm[kc + 9];
            uint32_t afrag[2][4];
            uint32_t bfrag[4][2];
#pragma unroll
            for (int im = 0; im < 2; im++) {
                const __half* base = pa + (warpM * 32 + im * 16 + g) * HASTR + kk + 2 * t;
                float2 f0 = unpack_h2(*(const uint32_t*)(base));
                float2 f1 = unpack_h2(*(const uint32_t*)(base + 8 * HASTR));
                float2 f2 = unpack_h2(*(const uint32_t*)(base + 8));
                float2 f3 = unpack_h2(*(const uint32_t*)(base + 8 * HASTR + 8));
                afrag[im][0] = pack_h2(fmaxf(fmaf(f0.x, s0.x, s0.y), 0.f),
                                       fmaxf(fmaf(f0.y, s1.x, s1.y), 0.f));
                afrag[im][1] = pack_h2(fmaxf(fmaf(f1.x, s0.x, s0.y), 0.f),
                                       fmaxf(fmaf(f1.y, s1.x, s1.y), 0.f));
                afrag[im][2] = pack_h2(fmaxf(fmaf(f2.x, s2.x, s2.y), 0.f),
                                       fmaxf(fmaf(f2.y, s3.x, s3.y), 0.f));
                afrag[im][3] = pack_h2(fmaxf(fmaf(f3.x, s2.x, s2.y), 0.f),
                                       fmaxf(fmaf(f3.y, s3.x, s3.y), 0.f));
            }
#pragma unroll
            for (int jn = 0; jn < 4; jn++) {
                const __half* base = pb + (warpN * 32 + jn * 8 + g) * HASTR + kk + 2 * t;
                bfrag[jn][0] = *(const uint32_t*)(base);
                bfrag[jn][1] = *(const uint32_t*)(base + 8);
            }
#pragma unroll
            for (int im = 0; im < 2; im++)
#pragma unroll
                for (int jn = 0; jn < 4; jn++) {
                    float4& c = acc[im][jn];
                    asm volatile(
                        "mma.sync.aligned.m16n8k16.row.col.f32.f16.f16.f32 "
                        "{%0,%1,%2,%3}, {%4,%5,%6,%7}, {%8,%9}, {%0,%1,%2,%3};"
                        : "+f"(c.x), "+f"(c.y), "+f"(c.z), "+f"(c.w)
                        : "r"(afrag[im][0]), "r"(afrag[im][1]),
                          "r"(afrag[im][2]), "r"(afrag[im][3]),
                          "r"(bfrag[jn][0]), "r"(bfrag[jn][1]));
                }
        }
        __syncthreads();
    }

#pragma unroll
    for (int jn = 0; jn < 4; jn++) {
        int col = bn + warpN * 32 + jn * 8 + 2 * t;
        float bx = bias[col], by = bias[col + 1];
#pragma unroll
        for (int im = 0; im < 2; im++) {
            int row0 = bm + warpM * 32 + im * 16 + g;
            float4 c = acc[im][jn];
            if (row0 < M)
                *(float2*)(C + (size_t)row0 * N + col) = make_float2(c.x + bx, c.y + by);
            if (row0 + 8 < M)
                *(float2*)(C + (size_t)(row0 + 8) * N + col) = make_float2(c.z + bx, c.w + by);
        }
    }
}

// --- stats -> per-col (scale, shift) ------------------------------------------
__global__ void k_bnprep(const float2* __restrict__ stats,
                         const float* __restrict__ gamma,
                         const float* __restrict__ beta,
                         float2* __restrict__ ss, int D, float invM) {
    int c = blockIdx.x * blockDim.x + threadIdx.x;
    if (c < D) {
        float mu = stats[c].x * invM;
        float var = stats[c].y * invM - mu * mu;
        float sc = gamma[c] * rsqrtf(var + EPS);
        ss[c] = make_float2(sc, beta[c] - mu * sc);
    }
}

// ---------------------------------------------------------------------------

extern "C" void kernel_launch(void* const* d_in, const int* in_sizes, int n_in,
                              void* d_out, int out_size) {
    const float* x      = (const float*)d_in[0];
    const void*  ei     = d_in[1];
    const float* W1     = (const float*)d_in[2];
    const float* b1     = (const float*)d_in[3];
    const float* gamma1 = (const float*)d_in[4];
    const float* beta1  = (const float*)d_in[5];
    const float* W2     = (const float*)d_in[6];
    const float* b2     = (const float*)d_in[7];
    const float* gamma2 = (const float*)d_in[8];
    const float* beta2  = (const float*)d_in[9];
    const float* Wl     = (const float*)d_in[10];
    const float* bl     = (const float*)d_in[11];

    const int H1   = in_sizes[3];
    const int H2   = in_sizes[7];
    const int DOUT = in_sizes[11];
    const int DIN  = in_sizes[2] / H1;
    const int N    = in_sizes[0] / DIN;
    const long long E = in_sizes[1] / 2;
    const float invM = 1.0f / (float)N;

    float *dinv;
    __half *agg1h, *agg2h, *h1, *h2, *w1t, *w2t, *wlt;
    float2 *stats1, *stats2, *ss1, *ss2;
    int *cnt, *rowptr, *cursor, *flag, *bsum;
    int2* adj;
    cudaGetSymbolAddress((void**)&dinv,   g_dinv);
    cudaGetSymbolAddress((void**)&cnt,    g_cnt);
    cudaGetSymbolAddress((void**)&rowptr, g_rowptr);
    cudaGetSymbolAddress((void**)&cursor, g_cursor);
    cudaGetSymbolAddress((void**)&bsum,   g_bsum);
    cudaGetSymbolAddress((void**)&adj,    g_adj);
    cudaGetSymbolAddress((void**)&agg1h,  g_agg1h);
    cudaGetSymbolAddress((void**)&agg2h,  g_agg2h);
    cudaGetSymbolAddress((void**)&h1,     g_h1);
    cudaGetSymbolAddress((void**)&h2,     g_h2);
    cudaGetSymbolAddress((void**)&w1t,    g_w1t);
    cudaGetSymbolAddress((void**)&w2t,    g_w2t);
    cudaGetSymbolAddress((void**)&wlt,    g_wlt);
    cudaGetSymbolAddress((void**)&stats1, g_stats1);
    cudaGetSymbolAddress((void**)&stats2, g_stats2);
    cudaGetSymbolAddress((void**)&ss1,    g_ss1);
    cudaGetSymbolAddress((void**)&ss2,    g_ss2);
    cudaGetSymbolAddress((void**)&flag,   g_flag32);

    float* out = (float*)d_out;

    cudaFuncSetAttribute(k_gemm_h,    cudaFuncAttributeMaxDynamicSharedMemorySize, SMEM_H);
    cudaFuncSetAttribute(k_gemm_finh, cudaFuncAttributeMaxDynamicSharedMemorySize, SMEM_FINH);

    const int scanBlocks = (N + SCAN_BLK - 1) / SCAN_BLK;
    const int aggBlocks = (int)(((long long)N * 32 + 255) / 256);
    const int mBlocks = (N + GBM - 1) / GBM;

    // prep (5 launches) -> agg1 is launch #6 (profiled next round)
    k_prep0<<<(N + 255) / 256, 256>>>((const int*)ei, E, cnt, N, stats1, stats2, H1, H2, flag);
    k_count<<<1024, 256>>>(ei, E, flag, cnt);
    k_scan_red<<<scanBlocks, SCAN_BLK>>>(cnt, bsum, N);
    k_scan_apply<<<scanBlocks, SCAN_BLK>>>(cnt, bsum, scanBlocks, rowptr, cursor, dinv, N);
    k_fill<<<1024, 256>>>(ei, E, flag, dinv, cursor, adj);

    k_agg1<<<aggBlocks, 256>>>(adj, rowptr, dinv, x, agg1h, N);

    k_cvtw<<<(H1 * H2 + 255) / 256, 256>>>(W1, W2, Wl, w1t, w2t, wlt,
                                           DIN, H1, H1, H2, H2, DOUT);

    {
        dim3 grid(H1 / GBN, mBlocks);
        k_gemm_h<<<grid, 256, SMEM_H>>>(agg1h, w1t, b1, h1, stats1, N, H1, DIN);
        k_bnprep<<<(H1 + 255) / 256, 256>>>(stats1, gamma1, beta1, ss1, H1, invM);
    }

    k_agg2<<<aggBlocks, 256>>>(adj, rowptr, dinv, h1, agg2h, N, ss1);
    {
        dim3 grid(H2 / GBN, mBlocks);
        k_gemm_h<<<grid, 256, SMEM_H>>>(agg2h, w2t, b2, h2, stats2, N, H2, H1);
        k_bnprep<<<(H2 + 255) / 256, 256>>>(stats2, gamma2, beta2, ss2, H2, invM);
    }

    {
        dim3 grid(DOUT / GBN, mBlocks);
        k_gemm_finh<<<grid, 256, SMEM_FINH>>>(h2, wlt, bl, out, ss2, N, DOUT, H2);
    }
}

// round 13
// speedup vs baseline: 1.0199x; 1.0004x over previous
#include <cuda_runtime.h>
#include <cuda_bf16.h>
#include <cuda_fp16.h>
#include <cstdint>

// ---------------------------------------------------------------------------
// GCN encoder: N=50000, E=500000, 128 -> 256 -> 512 -> 128
// CSR gather aggregation + fp16 mma.sync GEMMs (64x128 tiles, 3-stage pipe)
// ---------------------------------------------------------------------------

#define MAXN 50048
#define MAXE 524288
#define EPS 1e-5f
#define SCAN_BLK 1024

__device__ float  g_dinv[MAXN];
__device__ int    g_cnt[MAXN];
__device__ int    g_rowptr[MAXN + 1];
__device__ int    g_cursor[MAXN];
__device__ int    g_bsum[64];
__device__ int2   g_adj[MAXE];                 // (src, bits(w))
__device__ __half g_agg1h[(size_t)MAXN * 128];
__device__ __half g_agg2h[(size_t)MAXN * 256];
__device__ __half g_h1[(size_t)MAXN * 256];    // fp16 raw (pre-BN)
__device__ __half g_h2[(size_t)MAXN * 512];
__device__ __half g_w1t[256 * 128];            // fp16 W1^T [N][K]
__device__ __half g_w2t[512 * 256];
__device__ __half g_wlt[128 * 512];
__device__ float2 g_stats1[256];
__device__ float2 g_stats2[512];
__device__ float2 g_ss1[256];
__device__ float2 g_ss2[512];
__device__ int    g_flag32;

// ---------------------------------------------------------------------------

__device__ __forceinline__ void red_add_v2(float2* addr, float a, float b) {
    asm volatile("red.global.add.v2.f32 [%0], {%1,%2};"
                 :: "l"(addr), "f"(a), "f"(b) : "memory");
}

__device__ __forceinline__ int load_idx(const void* ei, long long pos, int is32) {
    if (is32) return ((const int*)ei)[pos];
    return (int)(((const long long*)ei)[pos]);
}

__device__ __forceinline__ uint32_t pack_h2(float lo, float hi) {
    uint32_t u;
    asm("cvt.rn.f16x2.f32 %0, %1, %2;" : "=r"(u) : "f"(hi), "f"(lo));
    return u;
}

__device__ __forceinline__ float2 unpack_h2(uint32_t u) {
    __half2 h = *(__half2*)&u;
    return __half22float2(h);
}

__device__ __forceinline__ void cp_async16(void* sptr, const void* gptr, int src_bytes) {
    uint32_t sa = (uint32_t)__cvta_generic_to_shared(sptr);
    asm volatile("cp.async.cg.shared.global [%0], [%1], 16, %2;"
                 :: "r"(sa), "l"(gptr), "r"(src_bytes));
}

// --- prep0 (+fused dtype detect on block 0): zero cnt + stats ----------------
__global__ void k_prep0(const int* __restrict__ ei32, long long E,
                        int* cnt, int n, float2* st1, float2* st2,
                        int d1, int d2, int* flag) {
    int i = blockIdx.x * blockDim.x + threadIdx.x;
    if (blockIdx.x == 0) {
        long long lim = E < 8192 ? E : 8192;
        int any = 0;
        for (long long j = threadIdx.x; j < lim; j += blockDim.x)
            if (ei32[2 * j + 1] != 0) any = 1;
        if (any) atomicOr(flag, 1);
    }
    if (i < n) cnt[i] = 0;
    if (i < d1) st1[i] = make_float2(0.f, 0.f);
    if (i < d2) st2[i] = make_float2(0.f, 0.f);
}

// --- in-degree counts ---------------------------------------------------------
__global__ void k_count(const void* ei, long long E, const int* flag, int* cnt) {
    long long i = blockIdx.x * (long long)blockDim.x + threadIdx.x;
    long long stride = (long long)gridDim.x * blockDim.x;
    int is32 = *flag;
    for (; i < E; i += stride) {
        int d = load_idx(ei, E + i, is32);
        atomicAdd(&cnt[d], 1);
    }
}

// --- scan pass 1 ---------------------------------------------------------------
__global__ __launch_bounds__(SCAN_BLK) void k_scan_red(const int* __restrict__ cnt,
                                                       int* __restrict__ bsum, int n) {
    int i = blockIdx.x * SCAN_BLK + threadIdx.x;
    int v = (i < n) ? cnt[i] : 0;
    int lane = threadIdx.x & 31, wid = threadIdx.x >> 5;
#pragma unroll
    for (int off = 16; off; off >>= 1) v += __shfl_xor_sync(0xffffffffu, v, off);
    __shared__ int ws[32];
    if (lane == 0) ws[wid] = v;
    __syncthreads();
    if (wid == 0) {
        v = ws[lane];
#pragma unroll
        for (int off = 16; off; off >>= 1) v += __shfl_xor_sync(0xffffffffu, v, off);
        if (lane == 0) bsum[blockIdx.x] = v;
    }
}

// --- scan pass 2 ---------------------------------------------------------------
__global__ __launch_bounds__(SCAN_BLK) void k_scan_apply(const int* __restrict__ cnt,
                                                         const int* __restrict__ bsum, int nb,
                                                         int* __restrict__ rowptr,
                                                         int* __restrict__ cursor,
                                                         float* __restrict__ dinv, int n) {
    int tid = threadIdx.x;
    int lane = tid & 31, wid = tid >> 5;
    __shared__ int ws[32];
    __shared__ int s_off;

    int b = (tid < nb && tid < blockIdx.x) ? bsum[tid] : 0;
#pragma unroll
    for (int off = 16; off; off >>= 1) b += __shfl_xor_sync(0xffffffffu, b, off);
    if (lane == 0) ws[wid] = b;
    __syncthreads();
    if (wid == 0) {
        int w = ws[lane];
#pragma unroll
        for (int off = 16; off; off >>= 1) w += __shfl_xor_sync(0xffffffffu, w, off);
        if (lane == 0) s_off = w;
    }
    __syncthreads();
    int offset = s_off;
    __syncthreads();

    int i = blockIdx.x * SCAN_BLK + tid;
    int v = (i < n) ? cnt[i] : 0;
    int x = v;
#pragma unroll
    for (int off = 1; off < 32; off <<= 1) {
        int y = __shfl_up_sync(0xffffffffu, x, off);
        if (lane >= off) x += y;
    }
    if (lane == 31) ws[wid] = x;
    __syncthreads();
    if (wid == 0) {
        int w = ws[lane];
#pragma unroll
        for (int off = 1; off < 32; off <<= 1) {
            int y = __shfl_up_sync(0xffffffffu, w, off);
            if (lane >= off) w += y;
        }
        ws[lane] = w;
    }
    __syncthreads();
    int incl = x + (wid > 0 ? ws[wid - 1] : 0);
    int excl = incl - v + offset;
    if (i < n) {
        rowptr[i] = excl;
        cursor[i] = excl;
        dinv[i] = rsqrtf((float)v + 1.0f);
        if (i == n - 1) rowptr[n] = excl + v;
    }
}

// --- bucket-fill adjacency -------------------------------------------------------
__global__ void k_fill(const void* __restrict__ ei, long long E, const int* flag,
                       const float* __restrict__ dinv, int* __restrict__ cursor,
                       int2* __restrict__ adj) {
    long long i = blockIdx.x * (long long)blockDim.x + threadIdx.x;
    long long stride = (long long)gridDim.x * blockDim.x;
    int is32 = *flag;
    for (; i < E; i += stride) {
        int s = load_idx(ei, i, is32);
        int d = load_idx(ei, E + i, is32);
        float w = dinv[s] * dinv[d];
        int pos = atomicAdd(&cursor[d], 1);
        adj[pos] = make_int2(s, __float_as_int(w));
    }
}

// --- weight convert: all three -> fp16 transposed [N][K] --------------------------
__global__ void k_cvtw(const float* __restrict__ W1, const float* __restrict__ W2,
                       const float* __restrict__ W3,
                       __half* __restrict__ t1, __half* __restrict__ t2,
                       __half* __restrict__ t3,
                       int K1, int N1, int K2, int N2, int K3, int N3) {
    int i = blockIdx.x * blockDim.x + threadIdx.x;
    if (i < K1 * N1) {
        int k = i / N1, n = i % N1;
        t1[n * K1 + k] = __float2half_rn(W1[i]);
    }
    if (i < K2 * N2) {
        int k = i / N2, n = i % N2;
        t2[n * K2 + k] = __float2half_rn(W2[i]);
    }
    if (i < K3 * N3) {
        int k = i / N3, n = i % N3;
        t3[n * K3 + k] = __float2half_rn(W3[i]);
    }
}

// --- agg layer 1: fp32 x in, fp16 out (R7) ----------------------------------------
__global__ __launch_bounds__(256) void k_agg1(const int2* __restrict__ adj,
                                              const int* __restrict__ rowptr,
                                              const float* __restrict__ dinv,
                                              const float* __restrict__ X,
                                              __half* __restrict__ out, int N) {
    int node = (blockIdx.x * blockDim.x + threadIdx.x) >> 5;
    int lane = threadIdx.x & 31;
    if (node >= N) return;
    float w0 = dinv[node]; w0 *= w0;
    float4 a = ((const float4*)(X + (size_t)node * 128))[lane];
    float4 acc = make_float4(a.x * w0, a.y * w0, a.z * w0, a.w * w0);
    int j = rowptr[node], end = rowptr[node + 1];
    int2 e = (j < end) ? adj[j] : make_int2(0, 0);
    for (; j < end; j++) {
        int2 cur = e;
        if (j + 1 < end) e = adj[j + 1];
        float w = __int_as_float(cur.y);
        float4 s = ((const float4*)(X + (size_t)cur.x * 128))[lane];
        acc.x += w * s.x; acc.y += w * s.y;
        acc.z += w * s.z; acc.w += w * s.w;
    }
    ((uint2*)(out + (size_t)node * 128))[lane] =
        make_uint2(pack_h2(acc.x, acc.y), pack_h2(acc.z, acc.w));
}

// --- agg layer 2: fp16 h1 in (BN+ReLU fused), fp16 out (R7) -----------------------
__global__ __launch_bounds__(256) void k_agg2(const int2* __restrict__ adj,
                                              const int* __restrict__ rowptr,
                                              const float* __restrict__ dinv,
                                              const __half* __restrict__ X,
                                              __half* __restrict__ out, int N,
                                              const float2* __restrict__ ss) {
    int node = (blockIdx.x * blockDim.x + threadIdx.x) >> 5;
    int lane = threadIdx.x & 31;
    if (node >= N) return;
    float2 sr[8];
#pragma unroll
    for (int j = 0; j < 8; j++) sr[j] = ss[lane * 8 + j];

    float acc[8];
    float w0 = dinv[node]; w0 *= w0;
    {
        uint4 u = ((const uint4*)(X + (size_t)node * 256))[lane];
        float2 f0 = unpack_h2(u.x), f1 = unpack_h2(u.y);
        float2 f2 = unpack_h2(u.z), f3 = unpack_h2(u.w);
        float f[8] = {f0.x, f0.y, f1.x, f1.y, f2.x, f2.y, f3.x, f3.y};
#pragma unroll
        for (int j = 0; j < 8; j++)
            acc[j] = w0 * fmaxf(fmaf(f[j], sr[j].x, sr[j].y), 0.f);
    }
    int j = rowptr[node], end = rowptr[node + 1];
    int2 e = (j < end) ? adj[j] : make_int2(0, 0);
    for (; j < end; j++) {
        int2 cur = e;
        if (j + 1 < end) e = adj[j + 1];
        float w = __int_as_float(cur.y);
        uint4 u = ((const uint4*)(X + (size_t)cur.x * 256))[lane];
        float2 f0 = unpack_h2(u.x), f1 = unpack_h2(u.y);
        float2 f2 = unpack_h2(u.z), f3 = unpack_h2(u.w);
        float f[8] = {f0.x, f0.y, f1.x, f1.y, f2.x, f2.y, f3.x, f3.y};
#pragma unroll
        for (int jj = 0; jj < 8; jj++)
            acc[jj] += w * fmaxf(fmaf(f[jj], sr[jj].x, sr[jj].y), 0.f);
    }
    uint4 o;
    o.x = pack_h2(acc[0], acc[1]);
    o.y = pack_h2(acc[2], acc[3]);
    o.z = pack_h2(acc[4], acc[5]);
    o.w = pack_h2(acc[6], acc[7]);
    ((uint4*)(out + (size_t)node * 256))[lane] = o;
}

// ---------------------------------------------------------------------------
// fp16 mma.sync GEMM, CTA tile 64x128, 8 warps (32x32), 3-stage cp.async
// pipeline, ONE __syncthreads per k-iter. Fused bias + fp32 BN stats, fp16 C.
// ---------------------------------------------------------------------------
#define GBM 64
#define GBN 128
#define HASTR 40
#define ASZ2 (64 * HASTR)          // halves per A stage
#define BSZ2 (128 * HASTR)         // halves per B stage
#define STG 3
#define SMEM_H ((STG * (ASZ2 + BSZ2)) * 2)
#define SMEM_FINH (SMEM_H + 512 * 8)

__global__ __launch_bounds__(256) void k_gemm_h(const __half* __restrict__ A,
                                                const __half* __restrict__ Bt,
                                                const float* __restrict__ bias,
                                                __half* __restrict__ C,
                                                float2* __restrict__ stats,
                                                int M, int N, int K) {
    extern __shared__ __half smh[];
    __half* As = smh;                    // STG stages of ASZ2
    __half* Bs = smh + STG * ASZ2;       // STG stages of BSZ2

    const int tid  = threadIdx.x;
    const int lane = tid & 31;
    const int warpId = tid >> 5;
    const int warpM = warpId & 1;
    const int warpN = warpId >> 1;
    const int g = lane >> 2;
    const int t = lane & 3;
    const int bm = blockIdx.y * GBM;
    const int bn = blockIdx.x * GBN;

    const int l_row = tid >> 2;
    const int l_chk = (tid & 3) * 8;

    float4 acc[2][4];
#pragma unroll
    for (int i = 0; i < 2; i++)
#pragma unroll
        for (int j = 0; j < 4; j++)
            acc[i][j] = make_float4(0.f, 0.f, 0.f, 0.f);

    auto load_stage = [&](int stg, int k0) {
        __half* pa = As + stg * ASZ2;
        __half* pb = Bs + stg * BSZ2;
        {
            int row = l_row;
            int gm = bm + row;
            int ok = (gm < M) ? 16 : 0;
            int gmc = min(gm, M - 1);
            cp_async16(pa + row * HASTR + l_chk, A + (size_t)gmc * K + k0 + l_chk, ok);
        }
#pragma unroll
        for (int i = 0; i < 2; i++) {
            int row = i * 64 + l_row;
            cp_async16(pb + row * HASTR + l_chk, Bt + (size_t)(bn + row) * K + k0 + l_chk, 16);
        }
        asm volatile("cp.async.commit_group;");
    };

    const int nk = K / 32;
    load_stage(0, 0);
    if (nk > 1) load_stage(1, 32);

    for (int tk = 0; tk < nk; tk++) {
        if (tk + 1 < nk) asm volatile("cp.async.wait_group 1;");
        else             asm volatile("cp.async.wait_group 0;");
        __syncthreads();
        if (tk + 2 < nk) load_stage((tk + 2) % STG, (tk + 2) * 32);

        const __half* pa = As + (tk % STG) * ASZ2;
        const __half* pb = Bs + (tk % STG) * BSZ2;
#pragma unroll
        for (int kk = 0; kk < 32; kk += 16) {
            uint32_t afrag[2][4];
            uint32_t bfrag[4][2];
#pragma unroll
            for (int im = 0; im < 2; im++) {
                const __half* base = pa + (warpM * 32 + im * 16 + g) * HASTR + kk + 2 * t;
                afrag[im][0] = *(const uint32_t*)(base);
                afrag[im][1] = *(const uint32_t*)(base + 8 * HASTR);
                afrag[im][2] = *(const uint32_t*)(base + 8);
                afrag[im][3] = *(const uint32_t*)(base + 8 * HASTR + 8);
            }
#pragma unroll
            for (int jn = 0; jn < 4; jn++) {
                const __half* base = pb + (warpN * 32 + jn * 8 + g) * HASTR + kk + 2 * t;
                bfrag[jn][0] = *(const uint32_t*)(base);
                bfrag[jn][1] = *(const uint32_t*)(base + 8);
            }
#pragma unroll
            for (int im = 0; im < 2; im++)
#pragma unroll
                for (int jn = 0; jn < 4; jn++) {
                    float4& c = acc[im][jn];
                    asm volatile(
                        "mma.sync.aligned.m16n8k16.row.col.f32.f16.f16.f32 "
                        "{%0,%1,%2,%3}, {%4,%5,%6,%7}, {%8,%9}, {%0,%1,%2,%3};"
                        : "+f"(c.x), "+f"(c.y), "+f"(c.z), "+f"(c.w)
                        : "r"(afrag[im][0]), "r"(afrag[im][1]),
                          "r"(afrag[im][2]), "r"(afrag[im][3]),
                          "r"(bfrag[jn][0]), "r"(bfrag[jn][1]));
                }
        }
    }

#pragma unroll
    for (int jn = 0; jn < 4; jn++) {
        int col = bn + warpN * 32 + jn * 8 + 2 * t;
        float bx = bias[col], by = bias[col + 1];
        float s0 = 0.f, q0 = 0.f, s1 = 0.f, q1 = 0.f;
#pragma unroll
        for (int im = 0; im < 2; im++) {
            int row0 = bm + warpM * 32 + im * 16 + g;
            float4 c = acc[im][jn];
            if (row0 < M) {
                float ox = c.x + bx, oy = c.y + by;
                *(uint32_t*)(C + (size_t)row0 * N + col) = pack_h2(ox, oy);
                s0 += ox; q0 += ox * ox; s1 += oy; q1 += oy * oy;
            }
            if (row0 + 8 < M) {
                float oz = c.z + bx, ow = c.w + by;
                *(uint32_t*)(C + (size_t)(row0 + 8) * N + col) = pack_h2(oz, ow);
                s0 += oz; q0 += oz * oz; s1 += ow; q1 += ow * ow;
            }
        }
#pragma unroll
        for (int m = 4; m < 32; m <<= 1) {
            s0 += __shfl_xor_sync(0xffffffffu, s0, m);
            q0 += __shfl_xor_sync(0xffffffffu, q0, m);
            s1 += __shfl_xor_sync(0xffffffffu, s1, m);
            q1 += __shfl_xor_sync(0xffffffffu, q1, m);
        }
        if (g == 0) {
            red_add_v2(&stats[col], s0, q0);
            red_add_v2(&stats[col + 1], s1, q1);
        }
    }
}

// ---------------------------------------------------------------------------
// Final fp16 GEMM, 64x128 tile, 3-stage pipe: BN2+ReLU at frag build, fp32 out.
// ---------------------------------------------------------------------------
__global__ __launch_bounds__(256) void k_gemm_finh(const __half* __restrict__ A,
                                                   const __half* __restrict__ Bt,
                                                   const float* __restrict__ bias,
                                                   float* __restrict__ C,
                                                   const float2* __restrict__ ssA,
                                                   int M, int N, int K) {
    extern __shared__ __half smh[];
    __half* As = smh;
    __half* Bs = smh + STG * ASZ2;
    float2* ssm = (float2*)(smh + STG * (ASZ2 + BSZ2));

    const int tid  = threadIdx.x;
    const int lane = tid & 31;
    const int warpId = tid >> 5;
    const int warpM = warpId & 1;
    const int warpN = warpId >> 1;
    const int g = lane >> 2;
    const int t = lane & 3;
    const int bm = blockIdx.y * GBM;
    const int bn = blockIdx.x * GBN;

    for (int c = tid; c < K; c += 256) ssm[c] = ssA[c];

    const int l_row = tid >> 2;
    const int l_chk = (tid & 3) * 8;

    float4 acc[2][4];
#pragma unroll
    for (int i = 0; i < 2; i++)
#pragma unroll
        for (int j = 0; j < 4; j++)
            acc[i][j] = make_float4(0.f, 0.f, 0.f, 0.f);

    auto load_stage = [&](int stg, int k0) {
        __half* pa = As + stg * ASZ2;
        __half* pb = Bs + stg * BSZ2;
        {
            int row = l_row;
            int gm = bm + row;
            int ok = (gm < M) ? 16 : 0;
            int gmc = min(gm, M - 1);
            cp_async16(pa + row * HASTR + l_chk, A + (size_t)gmc * K + k0 + l_chk, ok);
        }
#pragma unroll
        for (int i = 0; i < 2; i++) {
            int row = i * 64 + l_row;
            cp_async16(pb + row * HASTR + l_chk, Bt + (size_t)(bn + row) * K + k0 + l_chk, 16);
        }
        asm volatile("cp.async.commit_group;");
    };

    const int nk = K / 32;
    load_stage(0, 0);
    if (nk > 1) load_stage(1, 32);

    for (int tk = 0; tk < nk; tk++) {
        if (tk + 1 < nk) asm volatile("cp.async.wait_group 1;");
        else             asm volatile("cp.async.wait_group 0;");
        __syncthreads();
        if (tk + 2 < nk) load_stage((tk + 2) % STG, (tk + 2) * 32);

        const __half* pa = As + (tk % STG) * ASZ2;
        const __half* pb = Bs + (tk % STG) * BSZ2;
        const int kbase = tk * 32;
#pragma unroll
        for (int kk = 0; kk < 32; kk += 16) {
            int kc = kbase + kk + 2 * t;
            float2 s0 = ssm[kc],     s1 = ssm[kc + 1];
            float2 s2 = ssm[kc + 8], s3 = ssm[kc + 9];
            uint32_t afrag[2][4];
            uint32_t bfrag[4][2];
#pragma unroll
            for (int im = 0; im < 2; im++) {
                const __half* base = pa + (warpM * 32 + im * 16 + g) * HASTR + kk + 2 * t;
                float2 f0 = unpack_h2(*(const uint32_t*)(base));
                float2 f1 = unpack_h2(*(const uint32_t*)(base + 8 * HASTR));
                float2 f2 = unpack_h2(*(const uint32_t*)(base + 8));
                float2 f3 = unpack_h2(*(const uint32_t*)(base + 8 * HASTR + 8));
                afrag[im][0] = pack_h2(fmaxf(fmaf(f0.x, s0.x, s0.y), 0.f),
                                       fmaxf(fmaf(f0.y, s1.x, s1.y), 0.f));
                afrag[im][1] = pack_h2(fmaxf(fmaf(f1.x, s0.x, s0.y), 0.f),
                                       fmaxf(fmaf(f1.y, s1.x, s1.y), 0.f));
                afrag[im][2] = pack_h2(fmaxf(fmaf(f2.x, s2.x, s2.y), 0.f),
                                       fmaxf(fmaf(f2.y, s3.x, s3.y), 0.f));
                afrag[im][3] = pack_h2(fmaxf(fmaf(f3.x, s2.x, s2.y), 0.f),
                                       fmaxf(fmaf(f3.y, s3.x, s3.y), 0.f));
            }
#pragma unroll
            for (int jn = 0; jn < 4; jn++) {
                const __half* base = pb + (warpN * 32 + jn * 8 + g) * HASTR + kk + 2 * t;
                bfrag[jn][0] = *(const uint32_t*)(base);
                bfrag[jn][1] = *(const uint32_t*)(base + 8);
            }
#pragma unroll
            for (int im = 0; im < 2; im++)
#pragma unroll
                for (int jn = 0; jn < 4; jn++) {
                    float4& c = acc[im][jn];
                    asm volatile(
                        "mma.sync.aligned.m16n8k16.row.col.f32.f16.f16.f32 "
                        "{%0,%1,%2,%3}, {%4,%5,%6,%7}, {%8,%9}, {%0,%1,%2,%3};"
                        : "+f"(c.x), "+f"(c.y), "+f"(c.z), "+f"(c.w)
                        : "r"(afrag[im][0]), "r"(afrag[im][1]),
                          "r"(afrag[im][2]), "r"(afrag[im][3]),
                          "r"(bfrag[jn][0]), "r"(bfrag[jn][1]));
                }
        }
    }

#pragma unroll
    for (int jn = 0; jn < 4; jn++) {
        int col = bn + warpN * 32 + jn * 8 + 2 * t;
        float bx = bias[col], by = bias[col + 1];
#pragma unroll
        for (int im = 0; im < 2; im++) {
            int row0 = bm + warpM * 32 + im * 16 + g;
            float4 c = acc[im][jn];
            if (row0 < M)
                *(float2*)(C + (size_t)row0 * N + col) = make_float2(c.x + bx, c.y + by);
            if (row0 + 8 < M)
                *(float2*)(C + (size_t)(row0 + 8) * N + col) = make_float2(c.z + bx, c.w + by);
        }
    }
}

// --- stats -> per-col (scale, shift) ------------------------------------------
__global__ void k_bnprep(const float2* __restrict__ stats,
                         const float* __restrict__ gamma,
                         const float* __restrict__ beta,
                         float2* __restrict__ ss, int D, float invM) {
    int c = blockIdx.x * blockDim.x + threadIdx.x;
    if (c < D) {
        float mu = stats[c].x * invM;
        float var = stats[c].y * invM - mu * mu;
        float sc = gamma[c] * rsqrtf(var + EPS);
        ss[c] = make_float2(sc, beta[c] - mu * sc);
    }
}

// ---------------------------------------------------------------------------

extern "C" void kernel_launch(void* const* d_in, const int* in_sizes, int n_in,
                              void* d_out, int out_size) {
    const float* x      = (const float*)d_in[0];
    const void*  ei     = d_in[1];
    const float* W1     = (const float*)d_in[2];
    const float* b1     = (const float*)d_in[3];
    const float* gamma1 = (const float*)d_in[4];
    const float* beta1  = (const float*)d_in[5];
    const float* W2     = (const float*)d_in[6];
    const float* b2     = (const float*)d_in[7];
    const float* gamma2 = (const float*)d_in[8];
    const float* beta2  = (const float*)d_in[9];
    const float* Wl     = (const float*)d_in[10];
    const float* bl     = (const float*)d_in[11];

    const int H1   = in_sizes[3];
    const int H2   = in_sizes[7];
    const int DOUT = in_sizes[11];
    const int DIN  = in_sizes[2] / H1;
    const int N    = in_sizes[0] / DIN;
    const long long E = in_sizes[1] / 2;
    const float invM = 1.0f / (float)N;

    float *dinv;
    __half *agg1h, *agg2h, *h1, *h2, *w1t, *w2t, *wlt;
    float2 *stats1, *stats2, *ss1, *ss2;
    int *cnt, *rowptr, *cursor, *flag, *bsum;
    int2* adj;
    cudaGetSymbolAddress((void**)&dinv,   g_dinv);
    cudaGetSymbolAddress((void**)&cnt,    g_cnt);
    cudaGetSymbolAddress((void**)&rowptr, g_rowptr);
    cudaGetSymbolAddress((void**)&cursor, g_cursor);
    cudaGetSymbolAddress((void**)&bsum,   g_bsum);
    cudaGetSymbolAddress((void**)&adj,    g_adj);
    cudaGetSymbolAddress((void**)&agg1h,  g_agg1h);
    cudaGetSymbolAddress((void**)&agg2h,  g_agg2h);
    cudaGetSymbolAddress((void**)&h1,     g_h1);
    cudaGetSymbolAddress((void**)&h2,     g_h2);
    cudaGetSymbolAddress((void**)&w1t,    g_w1t);
    cudaGetSymbolAddress((void**)&w2t,    g_w2t);
    cudaGetSymbolAddress((void**)&wlt,    g_wlt);
    cudaGetSymbolAddress((void**)&stats1, g_stats1);
    cudaGetSymbolAddress((void**)&stats2, g_stats2);
    cudaGetSymbolAddress((void**)&ss1,    g_ss1);
    cudaGetSymbolAddress((void**)&ss2,    g_ss2);
    cudaGetSymbolAddress((void**)&flag,   g_flag32);

    float* out = (float*)d_out;

    cudaFuncSetAttribute(k_gemm_h,    cudaFuncAttributeMaxDynamicSharedMemorySize, SMEM_H);
    cudaFuncSetAttribute(k_gemm_finh, cudaFuncAttributeMaxDynamicSharedMemorySize, SMEM_FINH);

    const int scanBlocks = (N + SCAN_BLK - 1) / SCAN_BLK;
    const int aggBlocks = (int)(((long long)N * 32 + 255) / 256);
    const int mBlocks = (N + GBM - 1) / GBM;

    // prep
    k_prep0<<<(N + 255) / 256, 256>>>((const int*)ei, E, cnt, N, stats1, stats2, H1, H2, flag);
    k_count<<<1024, 256>>>(ei, E, flag, cnt);
    k_scan_red<<<scanBlocks, SCAN_BLK>>>(cnt, bsum, N);
    k_scan_apply<<<scanBlocks, SCAN_BLK>>>(cnt, bsum, scanBlocks, rowptr, cursor, dinv, N);
    k_fill<<<1024, 256>>>(ei, E, flag, dinv, cursor, adj);

    k_agg1<<<aggBlocks, 256>>>(adj, rowptr, dinv, x, agg1h, N);

    k_cvtw<<<(H1 * H2 + 255) / 256, 256>>>(W1, W2, Wl, w1t, w2t, wlt,
                                           DIN, H1, H1, H2, H2, DOUT);

    {
        dim3 grid(H1 / GBN, mBlocks);
        k_gemm_h<<<grid, 256, SMEM_H>>>(agg1h, w1t, b1, h1, stats1, N, H1, DIN);
        k_bnprep<<<(H1 + 255) / 256, 256>>>(stats1, gamma1, beta1, ss1, H1, invM);
    }

    k_agg2<<<aggBlocks, 256>>>(adj, rowptr, dinv, h1, agg2h, N, ss1);
    {
        dim3 grid(H2 / GBN, mBlocks);
        k_gemm_h<<<grid, 256, SMEM_H>>>(agg2h, w2t, b2, h2, stats2, N, H2, H1);
        k_bnprep<<<(H2 + 255) / 256, 256>>>(stats2, gamma2, beta2, ss2, H2, invM);
    }

    {
        dim3 grid(DOUT / GBN, mBlocks);
        k_gemm_finh<<<grid, 256, SMEM_FINH>>>(h2, wlt, bl, out, ss2, N, DOUT, H2);
    }
}